// round 7
// baseline (speedup 1.0000x reference)
#include <cuda_runtime.h>

// WeatherDifferentiatedAttention — fused, one CTA per (b,t) sequence.
// Round 6: bf16x2 smem storage for lane-varying streams (weights, h, K, V),
// fp32 math via f32x2 FMA; unpack = shift/mask on ALU pipe.

constexpr int NTHR = 512;
constexpr int NWARP = 16;
constexpr int NT = 200, NW = 100, CM = 256;

// regions: OFF_X fp32 [200][64]; KU/VU bf16x2 [208][34 u32]; WU weights bf16x2;
// PF fp32 probs (16 warps x 832) also hosts stage-5 Abuf.
constexpr int OFF_X = 0;
constexpr int KU = 12800;
constexpr int VU = KU + 208 * 34;          // 19872
constexpr int WU = VU + 208 * 34;          // 26944 ; size 10496 u32
constexpr int OPU = WU + 2176;             // stage-5 out_proj weights
constexpr int PF = WU + 10496;             // 37440
constexpr int SMEM_F = PF + 16 * 832;      // 50752 floats = 203008 B

typedef unsigned long long u64;
typedef unsigned u32t;

__device__ __forceinline__ float4 ld4(const float* p) {
    return *reinterpret_cast<const float4*>(p);
}
__device__ __forceinline__ void st4(float* p, const float4 v) {
    *reinterpret_cast<float4*>(p) = v;
}
__device__ __forceinline__ void st4u(float* p, const u64 lo, const u64 hi) {
    *reinterpret_cast<ulonglong2*>(p) = make_ulonglong2(lo, hi);
}
__device__ __forceinline__ uint2 ld2u(const u32t* p) {
    return *reinterpret_cast<const uint2*>(p);
}
__device__ __forceinline__ void st2u(u32t* p, const uint2 v) {
    *reinterpret_cast<uint2*>(p) = v;
}
__device__ __forceinline__ u64 pk1(float s) {
    u64 r; unsigned u = __float_as_uint(s);
    asm("mov.b64 %0, {%1, %1};" : "=l"(r) : "r"(u));
    return r;
}
__device__ __forceinline__ u64 pk2(float lo, float hi) {
    u64 r;
    asm("mov.b64 %0, {%1, %2};" : "=l"(r)
        : "r"(__float_as_uint(lo)), "r"(__float_as_uint(hi)));
    return r;
}
__device__ __forceinline__ void upk(u64 v, float& lo, float& hi) {
    unsigned a, b;
    asm("mov.b64 {%0, %1}, %2;" : "=r"(a), "=r"(b) : "l"(v));
    lo = __uint_as_float(a); hi = __uint_as_float(b);
}
// bf16x2 (u32) -> f32x2 (u64): bf16 bits are the top half of f32
__device__ __forceinline__ u64 bfpair(unsigned v) {
    unsigned lo = v << 16, hi = v & 0xffff0000u;
    u64 r;
    asm("mov.b64 %0, {%1, %2};" : "=l"(r) : "r"(lo), "r"(hi));
    return r;
}
__device__ __forceinline__ float bflo(unsigned v) { return __uint_as_float(v << 16); }
__device__ __forceinline__ float bfhi(unsigned v) { return __uint_as_float(v & 0xffff0000u); }
__device__ __forceinline__ unsigned packbf(float lo, float hi) {
    unsigned r;
    asm("cvt.rn.bf16x2.f32 %0, %1, %2;" : "=r"(r) : "f"(hi), "f"(lo));
    return r;
}
#define FMA2(acc, s2, wv) \
    asm("fma.rn.f32x2 %0, %1, %2, %0;" : "+l"(acc) : "l"(s2), "l"(wv))

__device__ __forceinline__ float hsum16(float v) {
    v += __shfl_xor_sync(0xffffffffu, v, 1);
    v += __shfl_xor_sync(0xffffffffu, v, 2);
    v += __shfl_xor_sync(0xffffffffu, v, 4);
    v += __shfl_xor_sync(0xffffffffu, v, 8);
    return v;
}
__device__ __forceinline__ float hmax16(float v) {
    v = fmaxf(v, __shfl_xor_sync(0xffffffffu, v, 1));
    v = fmaxf(v, __shfl_xor_sync(0xffffffffu, v, 2));
    v = fmaxf(v, __shfl_xor_sync(0xffffffffu, v, 4));
    v = fmaxf(v, __shfl_xor_sync(0xffffffffu, v, 8));
    return v;
}

__global__ __launch_bounds__(NTHR, 1) void wda_kernel(
    const float* __restrict__ turb, const float* __restrict__ weath,
    const float* __restrict__ w_t,  const float* __restrict__ b_t,
    const float* __restrict__ w_w,  const float* __restrict__ b_w,
    const float* __restrict__ g_t,  const float* __restrict__ be_t,
    const float* __restrict__ g_w,  const float* __restrict__ be_w,
    const float* __restrict__ w_qkv,const float* __restrict__ b_qkv,
    const float* __restrict__ w_ao, const float* __restrict__ b_ao,
    const float* __restrict__ w_op, const float* __restrict__ b_op,
    float* __restrict__ out)
{
    extern __shared__ float sm[];
    u32t* smu = reinterpret_cast<u32t*>(sm);
    const int tid  = threadIdx.x;
    const int warp = tid >> 5, lane = tid & 31;
    const int hh   = lane >> 4;
    const int hh2  = hh * 2;
    const int et   = lane & 15;
    const int e4   = et * 4;
    const int et2  = et * 2;
    const size_t s = blockIdx.x;
    const float* turb_s  = turb  + s * (size_t)(NT * CM);
    const float* weath_s = weath + s * (size_t)(NW * CM);
    float*       out_s   = out   + s * (size_t)(NT * CM);

    // zero V pad rows 200..207 (stage-4 context over-reads with p=0)
    for (int i = tid; i < 8 * 34; i += NTHR) smu[VU + 200 * 34 + i] = 0u;

    // ============ Stage 1: h = LN(x @ W^T + b), full-K single pass ========
#pragma unroll 1
    for (int src = 0; src < 2; ++src) {
        const float* inp = src ? weath_s : turb_s;
        const float* Wg  = src ? w_w  : w_t;
        const float* bg  = src ? b_w  : b_t;
        const float* gg  = src ? g_w  : g_t;
        const float* beg = src ? be_w : be_t;
        const int ngrp   = src ? 13 : 25;
        const int rmax   = src ? NW - 1 : NT - 1;
        u32t* hb = smu + (src ? KU : VU);
        const float4 bv = ld4(bg + e4), gv = ld4(gg + e4), ev = ld4(beg + e4);

        __syncthreads();
        // stage full wT [256 c][34 u32]: cols packed in bf16 pairs
        for (int idx = tid; idx < 256 * 32; idx += NTHR) {
            const int c = idx & 255, j = idx >> 8;
            smu[WU + c * 34 + j] =
                packbf(Wg[(2 * j) * 256 + c], Wg[(2 * j + 1) * 256 + c]);
        }
        __syncthreads();
#pragma unroll 1
        for (int g = warp; g < ngrp; g += NWARP) {
            const int r0 = g * 8 + hh * 4;
            const float* xp0 = inp + (size_t)min(r0 + 0, rmax) * CM;
            const float* xp1 = inp + (size_t)min(r0 + 1, rmax) * CM;
            const float* xp2 = inp + (size_t)min(r0 + 2, rmax) * CM;
            const float* xp3 = inp + (size_t)min(r0 + 3, rmax) * CM;
            u64 ac[4][2] = {};
#pragma unroll 2
            for (int k = 0; k < 256; k += 4) {
                const float4 x0 = ld4(xp0 + k), x1 = ld4(xp1 + k);
                const float4 x2 = ld4(xp2 + k), x3 = ld4(xp3 + k);
                const u32t* wp = smu + WU + k * 34 + et2;
                const uint2 c0 = ld2u(wp),      c1 = ld2u(wp + 34),
                            c2 = ld2u(wp + 68), c3 = ld2u(wp + 102);
                const u64 w00 = bfpair(c0.x), w01 = bfpair(c0.y);
                const u64 w10 = bfpair(c1.x), w11 = bfpair(c1.y);
                const u64 w20 = bfpair(c2.x), w21 = bfpair(c2.y);
                const u64 w30 = bfpair(c3.x), w31 = bfpair(c3.y);
#define S1ROW(i, xv) { \
                u64 s_ = pk1((xv).x); FMA2(ac[i][0], s_, w00); FMA2(ac[i][1], s_, w01); \
                s_ = pk1((xv).y);     FMA2(ac[i][0], s_, w10); FMA2(ac[i][1], s_, w11); \
                s_ = pk1((xv).z);     FMA2(ac[i][0], s_, w20); FMA2(ac[i][1], s_, w21); \
                s_ = pk1((xv).w);     FMA2(ac[i][0], s_, w30); FMA2(ac[i][1], s_, w31); }
                S1ROW(0, x0) S1ROW(1, x1) S1ROW(2, x2) S1ROW(3, x3)
#undef S1ROW
            }
#pragma unroll
            for (int i = 0; i < 4; ++i) {
                float y0, y1, y2, y3;
                upk(ac[i][0], y0, y1); upk(ac[i][1], y2, y3);
                y0 += bv.x; y1 += bv.y; y2 += bv.z; y3 += bv.w;
                const float mu = hsum16(y0 + y1 + y2 + y3) * 0.015625f;
                const float qq = hsum16(y0*y0 + y1*y1 + y2*y2 + y3*y3) * 0.015625f;
                const float rs = rsqrtf(qq - mu * mu + 1e-5f);
                y0 = (y0 - mu) * rs * gv.x + ev.x;
                y1 = (y1 - mu) * rs * gv.y + ev.y;
                y2 = (y2 - mu) * rs * gv.z + ev.z;
                y3 = (y3 - mu) * rs * gv.w + ev.w;
                uint2 hv; hv.x = packbf(y0, y1); hv.y = packbf(y2, y3);
                st2u(hb + (r0 + i) * 34 + et2, hv);
            }
        }
    }
    __syncthreads();

    // prestage stage-3 QKV weights (W region free; ordered by stage-2-end sync)
    for (int idx = tid; idx < 64 * 96; idx += NTHR) {
        const int d = idx & 63, j = idx >> 6;
        smu[WU + d * 98 + j] =
            packbf(w_qkv[(2 * j) * 64 + d], w_qkv[(2 * j + 1) * 64 + d]);
    }

    // ============ Stage 2: cross-attention ================================
    {
        float* P  = sm + PF + warp * 832;
        float* pA = P + hh2 * 112;
        float* pB = pA + 112;
        int moff[7];
#pragma unroll
        for (int j = 0; j < 7; ++j)
            moff[j] = KU + min(et + 16 * j, NW - 1) * 34;
#pragma unroll 1
        for (int g = warp; g < NT / 4; g += NWARP) {
            const int rA = g * 4 + hh2;
            const u32t* qpa = smu + VU + rA * 34;
            const u32t* qpb = qpa + 34;
            u64 la[7] = {}, lb[7] = {};
#pragma unroll 4
            for (int dc = 0; dc < 32; dc += 2) {
                const uint2 qa = ld2u(qpa + dc), qb = ld2u(qpb + dc);
                const u64 qa0 = bfpair(qa.x), qa1 = bfpair(qa.y);
                const u64 qb0 = bfpair(qb.x), qb1 = bfpair(qb.y);
#pragma unroll
                for (int j = 0; j < 7; ++j) {
                    const uint2 kv = ld2u(smu + moff[j] + dc);
                    const u64 k0 = bfpair(kv.x), k1 = bfpair(kv.y);
                    FMA2(la[j], qa0, k0); FMA2(la[j], qa1, k1);
                    FMA2(lb[j], qb0, k0); FMA2(lb[j], qb1, k1);
                }
            }
            float lA[7], lB[7];
#pragma unroll
            for (int j = 0; j < 7; ++j) {
                float lo, hi;
                upk(la[j], lo, hi); lA[j] = lo + hi;
                upk(lb[j], lo, hi); lB[j] = lo + hi;
            }
            float mA = -1e30f, mB = -1e30f;
#pragma unroll
            for (int j = 0; j < 7; ++j) {
                const bool ok = et + 16 * j < NW;
                lA[j] = ok ? lA[j] * 0.125f : -1e30f;
                lB[j] = ok ? lB[j] * 0.125f : -1e30f;
                mA = fmaxf(mA, lA[j]); mB = fmaxf(mB, lB[j]);
            }
            mA = hmax16(mA); mB = hmax16(mB);
            float sA = 0.f, sB = 0.f;
#pragma unroll
            for (int j = 0; j < 7; ++j) {
                const bool ok = et + 16 * j < NW;
                lA[j] = ok ? __expf(lA[j] - mA) : 0.f;
                lB[j] = ok ? __expf(lB[j] - mB) : 0.f;
                sA += lA[j]; sB += lB[j];
            }
            const float iA = 1.f / hsum16(sA), iB = 1.f / hsum16(sB);
#pragma unroll
            for (int j = 0; j < 7; ++j) {
                const int m = et + 16 * j;
                if (m < NW) { pA[m] = lA[j] * iA; pB[m] = lB[j] * iB; }
            }
            __syncwarp();
            u64 c0A = 0, c1A = 0, c0B = 0, c1B = 0;
#pragma unroll 5
            for (int m = 0; m < NW; m += 4) {
                const float4 pa = ld4(pA + m), pb = ld4(pB + m);
                const u32t* kp = smu + KU + m * 34 + et2;
                const uint2 m0 = ld2u(kp),      m1 = ld2u(kp + 34),
                            m2 = ld2u(kp + 68), m3 = ld2u(kp + 102);
                const u64 w00 = bfpair(m0.x), w01 = bfpair(m0.y);
                const u64 w10 = bfpair(m1.x), w11 = bfpair(m1.y);
                const u64 w20 = bfpair(m2.x), w21 = bfpair(m2.y);
                const u64 w30 = bfpair(m3.x), w31 = bfpair(m3.y);
                u64 s_;
                s_ = pk1(pa.x); FMA2(c0A, s_, w00); FMA2(c1A, s_, w01);
                s_ = pk1(pa.y); FMA2(c0A, s_, w10); FMA2(c1A, s_, w11);
                s_ = pk1(pa.z); FMA2(c0A, s_, w20); FMA2(c1A, s_, w21);
                s_ = pk1(pa.w); FMA2(c0A, s_, w30); FMA2(c1A, s_, w31);
                s_ = pk1(pb.x); FMA2(c0B, s_, w00); FMA2(c1B, s_, w01);
                s_ = pk1(pb.y); FMA2(c0B, s_, w10); FMA2(c1B, s_, w11);
                s_ = pk1(pb.z); FMA2(c0B, s_, w20); FMA2(c1B, s_, w21);
                s_ = pk1(pb.w); FMA2(c0B, s_, w30); FMA2(c1B, s_, w31);
            }
            st4u(sm + OFF_X + rA * 64 + e4, c0A, c1A);
            st4u(sm + OFF_X + (rA + 1) * 64 + e4, c0B, c1B);
            __syncwarp();
        }
    }
    __syncthreads();

    // ============ Stage 3: QKV projection ==================================
    {
        const float4 bq0 = ld4(b_qkv + e4), bq1 = ld4(b_qkv + 64 + e4),
                     bq2 = ld4(b_qkv + 128 + e4);
#pragma unroll 1
        for (int g = warp; g < NT / 4; g += NWARP) {
            const int rA = g * 4 + hh2;
            const float* xA = sm + OFF_X + rA * 64;
            const float* xB = xA + 64;
            u64 q0A = pk2(bq0.x, bq0.y), q1A = pk2(bq0.z, bq0.w);
            u64 k0A = pk2(bq1.x, bq1.y), k1A = pk2(bq1.z, bq1.w);
            u64 v0A = pk2(bq2.x, bq2.y), v1A = pk2(bq2.z, bq2.w);
            u64 q0B = q0A, q1B = q1A, k0B = k0A, k1B = k1A, v0B = v0A, v1B = v1A;
#pragma unroll 4
            for (int d = 0; d < 64; d += 4) {
                const float4 a = ld4(xA + d), b = ld4(xB + d);
#define QKV_STEP(xa, xb, dd) { \
                const u32t* wp = smu + WU + (d + dd) * 98 + et2; \
                const uint2 uq = ld2u(wp), uk = ld2u(wp + 32), uv = ld2u(wp + 64); \
                const u64 wq0 = bfpair(uq.x), wq1 = bfpair(uq.y); \
                const u64 wk0 = bfpair(uk.x), wk1 = bfpair(uk.y); \
                const u64 wv0 = bfpair(uv.x), wv1 = bfpair(uv.y); \
                const u64 sa_ = pk1(xa), sb_ = pk1(xb); \
                FMA2(q0A, sa_, wq0); FMA2(q1A, sa_, wq1); \
                FMA2(k0A, sa_, wk0); FMA2(k1A, sa_, wk1); \
                FMA2(v0A, sa_, wv0); FMA2(v1A, sa_, wv1); \
                FMA2(q0B, sb_, wq0); FMA2(q1B, sb_, wq1); \
                FMA2(k0B, sb_, wk0); FMA2(k1B, sb_, wk1); \
                FMA2(v0B, sb_, wv0); FMA2(v1B, sb_, wv1); }
                QKV_STEP(a.x, b.x, 0) QKV_STEP(a.y, b.y, 1)
                QKV_STEP(a.z, b.z, 2) QKV_STEP(a.w, b.w, 3)
#undef QKV_STEP
            }
            st4u(sm + OFF_X + rA * 64 + e4, q0A, q1A);      // q fp32, overwrites x
            st4u(sm + OFF_X + (rA + 1) * 64 + e4, q0B, q1B);
            float t0, t1, t2, t3;
            uint2 pr;
            upk(k0A, t0, t1); upk(k1A, t2, t3);
            pr.x = packbf(t0, t1); pr.y = packbf(t2, t3);
            st2u(smu + KU + rA * 34 + et2, pr);
            upk(k0B, t0, t1); upk(k1B, t2, t3);
            pr.x = packbf(t0, t1); pr.y = packbf(t2, t3);
            st2u(smu + KU + (rA + 1) * 34 + et2, pr);
            upk(v0A, t0, t1); upk(v1A, t2, t3);
            pr.x = packbf(t0, t1); pr.y = packbf(t2, t3);
            st2u(smu + VU + rA * 34 + et2, pr);
            upk(v0B, t0, t1); upk(v1B, t2, t3);
            pr.x = packbf(t0, t1); pr.y = packbf(t2, t3);
            st2u(smu + VU + (rA + 1) * 34 + et2, pr);
        }
    }
    __syncthreads();

    // prestage stage-5 weights (W free; stage 4 doesn't touch W)
    for (int idx = tid; idx < 64 * 32; idx += NTHR) {
        const int d = idx & 63, j = idx >> 6;
        smu[WU + d * 34 + j] =
            packbf(w_ao[(2 * j) * 64 + d], w_ao[(2 * j + 1) * 64 + d]);
    }
    for (int idx = tid; idx < 64 * 128; idx += NTHR) {
        const int e = idx & 63, j = idx >> 6;
        smu[OPU + e * 130 + j] =
            packbf(w_op[(2 * j) * 64 + e], w_op[(2 * j + 1) * 64 + e]);
    }

    // ============ Stage 4: 4-head self-attention (o overwrites q) ==========
    {
        float* P  = sm + PF + warp * 832;          // [4][208]
        float* pA = P + hh2 * 208;
        float* pB = pA + 208;
        const int ms = et >> 2, dd4 = (et & 3) * 4;
        int koff[13];
#pragma unroll
        for (int j = 0; j < 13; ++j)
            koff[j] = KU + min(et + 16 * j, NT - 1) * 34;
#pragma unroll 1
        for (int g = warp; g < NT / 4; g += NWARP) {
            const int rA = g * 4 + hh2;
            if (et < 8) { pA[200 + et] = 0.f; pB[200 + et] = 0.f; }
#pragma unroll 1
            for (int hd0 = 0; hd0 < 64; hd0 += 16) {
                const int hc = hd0 >> 1;
                const float* qA = sm + OFF_X + rA * 64 + hd0;
                const float* qB = qA + 64;
                float lA[13], lB[13];
#pragma unroll
                for (int j = 0; j < 13; ++j) { lA[j] = 0.f; lB[j] = 0.f; }
#pragma unroll
                for (int d = 0; d < 16; d += 4) {
                    const float4 a = ld4(qA + d), b = ld4(qB + d);
#pragma unroll
                    for (int j = 0; j < 13; ++j) {
                        const uint2 kv = ld2u(smu + koff[j] + hc + (d >> 1));
                        const float k0 = bflo(kv.x), k1 = bfhi(kv.x);
                        const float k2 = bflo(kv.y), k3 = bfhi(kv.y);
                        lA[j] = fmaf(a.w, k3, fmaf(a.z, k2,
                                fmaf(a.y, k1, fmaf(a.x, k0, lA[j]))));
                        lB[j] = fmaf(b.w, k3, fmaf(b.z, k2,
                                fmaf(b.y, k1, fmaf(b.x, k0, lB[j]))));
                    }
                }
                float mA = -1e30f, mB = -1e30f;
#pragma unroll
                for (int j = 0; j < 13; ++j) {
                    const bool ok = et + 16 * j < NT;
                    lA[j] = ok ? lA[j] * 0.25f : -1e30f;
                    lB[j] = ok ? lB[j] * 0.25f : -1e30f;
                    mA = fmaxf(mA, lA[j]); mB = fmaxf(mB, lB[j]);
                }
                mA = hmax16(mA); mB = hmax16(mB);
                float sA = 0.f, sB = 0.f;
#pragma unroll
                for (int j = 0; j < 13; ++j) {
                    const bool ok = et + 16 * j < NT;
                    lA[j] = ok ? __expf(lA[j] - mA) : 0.f;
                    lB[j] = ok ? __expf(lB[j] - mB) : 0.f;
                    sA += lA[j]; sB += lB[j];
                }
                const float iA = 1.f / hsum16(sA), iB = 1.f / hsum16(sB);
#pragma unroll
                for (int j = 0; j < 13; ++j) {
                    const int m = et + 16 * j;
                    if (m < NT) { pA[m] = lA[j] * iA; pB[m] = lB[j] * iB; }
                }
                __syncwarp();
                u64 o0A = 0, o1A = 0, o0B = 0, o1B = 0;
                const int m0 = ms * 52;
                const int vcol = hc + (et & 3) * 2;
#pragma unroll
                for (int mi = 0; mi < 52; mi += 4) {
                    const int m = m0 + mi;
                    const float4 pa = ld4(pA + m), pb = ld4(pB + m);
                    const u32t* vp = smu + VU + m * 34 + vcol;
                    const uint2 r0 = ld2u(vp),      r1 = ld2u(vp + 34),
                                r2 = ld2u(vp + 68), r3 = ld2u(vp + 102);
                    const u64 v00 = bfpair(r0.x), v01 = bfpair(r0.y);
                    const u64 v10 = bfpair(r1.x), v11 = bfpair(r1.y);
                    const u64 v20 = bfpair(r2.x), v21 = bfpair(r2.y);
                    const u64 v30 = bfpair(r3.x), v31 = bfpair(r3.y);
                    u64 s_;
                    s_ = pk1(pa.x); FMA2(o0A, s_, v00); FMA2(o1A, s_, v01);
                    s_ = pk1(pa.y); FMA2(o0A, s_, v10); FMA2(o1A, s_, v11);
                    s_ = pk1(pa.z); FMA2(o0A, s_, v20); FMA2(o1A, s_, v21);
                    s_ = pk1(pa.w); FMA2(o0A, s_, v30); FMA2(o1A, s_, v31);
                    s_ = pk1(pb.x); FMA2(o0B, s_, v00); FMA2(o1B, s_, v01);
                    s_ = pk1(pb.y); FMA2(o0B, s_, v10); FMA2(o1B, s_, v11);
                    s_ = pk1(pb.z); FMA2(o0B, s_, v20); FMA2(o1B, s_, v21);
                    s_ = pk1(pb.w); FMA2(o0B, s_, v30); FMA2(o1B, s_, v31);
                }
                float4 oA, oB;
                upk(o0A, oA.x, oA.y); upk(o1A, oA.z, oA.w);
                upk(o0B, oB.x, oB.y); upk(o1B, oB.z, oB.w);
#define RED48(c) { c += __shfl_xor_sync(0xffffffffu, c, 4); \
                   c += __shfl_xor_sync(0xffffffffu, c, 8); }
                RED48(oA.x) RED48(oA.y) RED48(oA.z) RED48(oA.w)
                RED48(oB.x) RED48(oB.y) RED48(oB.z) RED48(oB.w)
#undef RED48
                if (ms == 0) {
                    st4(sm + OFF_X + rA * 64 + hd0 + dd4, oA);
                    st4(sm + OFF_X + (rA + 1) * 64 + hd0 + dd4, oB);
                }
                __syncwarp();
            }
        }
    }
    __syncthreads();

    // ============ Stage 5: attn_out -> out_proj + residual =================
    {
        const float4 bao  = ld4(b_ao + e4);
        const float4 bop0 = ld4(b_op + e4),       bop1 = ld4(b_op + 64 + e4),
                     bop2 = ld4(b_op + 128 + e4), bop3 = ld4(b_op + 192 + e4);
        float* Abuf = sm + PF + warp * 832;       // probs region, dead now
#pragma unroll 1
        for (int g = warp; g < NT / 4; g += NWARP) {
            const int rA = g * 4 + hh2;
            const float* oA = sm + OFF_X + rA * 64;
            const float* oB = oA + 64;
            u64 a0A = pk2(bao.x, bao.y), a1A = pk2(bao.z, bao.w);
            u64 a0B = a0A, a1B = a1A;
#pragma unroll 4
            for (int d = 0; d < 64; d += 4) {
                const float4 a = ld4(oA + d), b = ld4(oB + d);
                const u32t* wp = smu + WU + d * 34 + et2;
                const uint2 c0 = ld2u(wp),      c1 = ld2u(wp + 34),
                            c2 = ld2u(wp + 68), c3 = ld2u(wp + 102);
                const u64 w00 = bfpair(c0.x), w01 = bfpair(c0.y);
                const u64 w10 = bfpair(c1.x), w11 = bfpair(c1.y);
                const u64 w20 = bfpair(c2.x), w21 = bfpair(c2.y);
                const u64 w30 = bfpair(c3.x), w31 = bfpair(c3.y);
                u64 s_;
                s_ = pk1(a.x); FMA2(a0A, s_, w00); FMA2(a1A, s_, w01);
                s_ = pk1(a.y); FMA2(a0A, s_, w10); FMA2(a1A, s_, w11);
                s_ = pk1(a.z); FMA2(a0A, s_, w20); FMA2(a1A, s_, w21);
                s_ = pk1(a.w); FMA2(a0A, s_, w30); FMA2(a1A, s_, w31);
                s_ = pk1(b.x); FMA2(a0B, s_, w00); FMA2(a1B, s_, w01);
                s_ = pk1(b.y); FMA2(a0B, s_, w10); FMA2(a1B, s_, w11);
                s_ = pk1(b.z); FMA2(a0B, s_, w20); FMA2(a1B, s_, w21);
                s_ = pk1(b.w); FMA2(a0B, s_, w30); FMA2(a1B, s_, w31);
            }
            st4u(Abuf + hh2 * 68 + e4, a0A, a1A);
            st4u(Abuf + hh2 * 68 + 68 + e4, a0B, a1B);
            __syncwarp();
            const float* tA = turb_s + (size_t)rA * CM;
            const float* tB = tA + CM;
            float* outA = out_s + (size_t)rA * CM;
            float* outB = outA + CM;
            u64 aA[8], aB[8];
            {
                float4 r;
                r = ld4(tA + e4);
                aA[0] = pk2(bop0.x + r.x, bop0.y + r.y); aA[1] = pk2(bop0.z + r.z, bop0.w + r.w);
                r = ld4(tA + 64 + e4);
                aA[2] = pk2(bop1.x + r.x, bop1.y + r.y); aA[3] = pk2(bop1.z + r.z, bop1.w + r.w);
                r = ld4(tA + 128 + e4);
                aA[4] = pk2(bop2.x + r.x, bop2.y + r.y); aA[5] = pk2(bop2.z + r.z, bop2.w + r.w);
                r = ld4(tA + 192 + e4);
                aA[6] = pk2(bop3.x + r.x, bop3.y + r.y); aA[7] = pk2(bop3.z + r.z, bop3.w + r.w);
                r = ld4(tB + e4);
                aB[0] = pk2(bop0.x + r.x, bop0.y + r.y); aB[1] = pk2(bop0.z + r.z, bop0.w + r.w);
                r = ld4(tB + 64 + e4);
                aB[2] = pk2(bop1.x + r.x, bop1.y + r.y); aB[3] = pk2(bop1.z + r.z, bop1.w + r.w);
                r = ld4(tB + 128 + e4);
                aB[4] = pk2(bop2.x + r.x, bop2.y + r.y); aB[5] = pk2(bop2.z + r.z, bop2.w + r.w);
                r = ld4(tB + 192 + e4);
                aB[6] = pk2(bop3.x + r.x, bop3.y + r.y); aB[7] = pk2(bop3.z + r.z, bop3.w + r.w);
            }
            const float* arowA = Abuf + hh2 * 68;
            const float* arowB = arowA + 68;
#pragma unroll 2
            for (int e = 0; e < 64; e += 4) {
                const float4 a = ld4(arowA + e), b = ld4(arowB + e);
#define OP_STEP(xa, xb, ee) { \
                const u32t* wp = smu + OPU + (e + ee) * 130 + et2; \
                const uint2 u0 = ld2u(wp),      u1 = ld2u(wp + 32), \
                            u2 = ld2u(wp + 64), u3 = ld2u(wp + 96); \
                const u64 w00 = bfpair(u0.x), w01 = bfpair(u0.y); \
                const u64 w10 = bfpair(u1.x), w11 = bfpair(u1.y); \
                const u64 w20 = bfpair(u2.x), w21 = bfpair(u2.y); \
                const u64 w30 = bfpair(u3.x), w31 = bfpair(u3.y); \
                const u64 sa_ = pk1(xa), sb_ = pk1(xb); \
                FMA2(aA[0], sa_, w00); FMA2(aA[1], sa_, w01); \
                FMA2(aA[2], sa_, w10); FMA2(aA[3], sa_, w11); \
                FMA2(aA[4], sa_, w20); FMA2(aA[5], sa_, w21); \
                FMA2(aA[6], sa_, w30); FMA2(aA[7], sa_, w31); \
                FMA2(aB[0], sb_, w00); FMA2(aB[1], sb_, w01); \
                FMA2(aB[2], sb_, w10); FMA2(aB[3], sb_, w11); \
                FMA2(aB[4], sb_, w20); FMA2(aB[5], sb_, w21); \
                FMA2(aB[6], sb_, w30); FMA2(aB[7], sb_, w31); }
                OP_STEP(a.x, b.x, 0) OP_STEP(a.y, b.y, 1)
                OP_STEP(a.z, b.z, 2) OP_STEP(a.w, b.w, 3)
#undef OP_STEP
            }
            st4u(outA + e4,       aA[0], aA[1]); st4u(outA + 64 + e4,  aA[2], aA[3]);
            st4u(outA + 128 + e4, aA[4], aA[5]); st4u(outA + 192 + e4, aA[6], aA[7]);
            st4u(outB + e4,       aB[0], aB[1]); st4u(outB + 64 + e4,  aB[2], aB[3]);
            st4u(outB + 128 + e4, aB[4], aB[5]); st4u(outB + 192 + e4, aB[6], aB[7]);
            __syncwarp();
        }
    }
}

extern "C" void kernel_launch(void* const* d_in, const int* in_sizes, int n_in,
                              void* d_out, int out_size)
{
    const float* turb  = (const float*)d_in[0];
    const float* weath = (const float*)d_in[1];
    const float* w_t   = (const float*)d_in[2];
    const float* b_t   = (const float*)d_in[3];
    const float* w_w   = (const float*)d_in[4];
    const float* b_w   = (const float*)d_in[5];
    const float* g_t   = (const float*)d_in[6];
    const float* be_t  = (const float*)d_in[7];
    const float* g_w   = (const float*)d_in[8];
    const float* be_w  = (const float*)d_in[9];
    const float* w_qkv = (const float*)d_in[10];
    const float* b_qkv = (const float*)d_in[11];
    const float* w_ao  = (const float*)d_in[12];
    const float* b_ao  = (const float*)d_in[13];
    const float* w_op  = (const float*)d_in[14];
    const float* b_op  = (const float*)d_in[15];
    float* out = (float*)d_out;

    const int S = in_sizes[0] / (NT * CM);   // 768
    const size_t smem = (size_t)SMEM_F * sizeof(float);
    cudaFuncSetAttribute(wda_kernel, cudaFuncAttributeMaxDynamicSharedMemorySize,
                         (int)smem);
    wda_kernel<<<S, NTHR, smem>>>(turb, weath, w_t, b_t, w_w, b_w,
                                  g_t, be_t, g_w, be_w, w_qkv, b_qkv,
                                  w_ao, b_ao, w_op, b_op, out);
}

// round 8
// speedup vs baseline: 1.0467x; 1.0467x over previous
#include <cuda_runtime.h>

// Round 8: 2 CTAs/SM. 256 thr, 110400B smem. bf16 smem everywhere lane-varying.

constexpr int NTHR = 256;
constexpr int NWARP = 8;
constexpr int NT = 200, NW = 100, CM = 256;

// u32 offsets
constexpr int XU   = 0;          // x/q/o bf16 [200][34]; S1 wchunk0 [128][34]
constexpr int KU   = 6800;       // h_w/K bf16 [208][34]; S5: opW [64][130]
constexpr int VU   = 13872;      // h_t/V bf16 [208][34]
constexpr int MISC = 20944;      // 6656: S1 wchunk1 / probs / S3 w / S5 aoW+Abuf
constexpr int ABF  = MISC + 2176;
constexpr int SMEM_U = 27600;    // 110400 bytes

typedef unsigned long long u64;
typedef unsigned u32t;

__device__ __forceinline__ float4 ld4(const float* p) {
    return *reinterpret_cast<const float4*>(p);
}
__device__ __forceinline__ void st4f(float* p, const u64 lo, const u64 hi) {
    *reinterpret_cast<ulonglong2*>(p) = make_ulonglong2(lo, hi);
}
__device__ __forceinline__ uint2 ld2u(const u32t* p) {
    return *reinterpret_cast<const uint2*>(p);
}
__device__ __forceinline__ void st2u(u32t* p, const uint2 v) {
    *reinterpret_cast<uint2*>(p) = v;
}
__device__ __forceinline__ u64 pk1(float s) {
    u64 r; unsigned u = __float_as_uint(s);
    asm("mov.b64 %0, {%1, %1};" : "=l"(r) : "r"(u));
    return r;
}
__device__ __forceinline__ u64 pk2(float lo, float hi) {
    u64 r;
    asm("mov.b64 %0, {%1, %2};" : "=l"(r)
        : "r"(__float_as_uint(lo)), "r"(__float_as_uint(hi)));
    return r;
}
__device__ __forceinline__ void upk(u64 v, float& lo, float& hi) {
    unsigned a, b;
    asm("mov.b64 {%0, %1}, %2;" : "=r"(a), "=r"(b) : "l"(v));
    lo = __uint_as_float(a); hi = __uint_as_float(b);
}
__device__ __forceinline__ u64 bfpair(unsigned v) {
    unsigned lo = v << 16, hi = v & 0xffff0000u;
    u64 r;
    asm("mov.b64 %0, {%1, %2};" : "=l"(r) : "r"(lo), "r"(hi));
    return r;
}
__device__ __forceinline__ u64 bcastlo(unsigned v) {
    unsigned t = v << 16; u64 r;
    asm("mov.b64 %0, {%1, %1};" : "=l"(r) : "r"(t));
    return r;
}
__device__ __forceinline__ u64 bcasthi(unsigned v) {
    unsigned t = v & 0xffff0000u; u64 r;
    asm("mov.b64 %0, {%1, %1};" : "=l"(r) : "r"(t));
    return r;
}
__device__ __forceinline__ float bflo(unsigned v) { return __uint_as_float(v << 16); }
__device__ __forceinline__ float bfhi(unsigned v) { return __uint_as_float(v & 0xffff0000u); }
__device__ __forceinline__ unsigned packbf(float lo, float hi) {
    unsigned r;
    asm("cvt.rn.bf16x2.f32 %0, %1, %2;" : "=r"(r) : "f"(hi), "f"(lo));
    return r;
}
#define FMA2(acc, s2, wv) \
    asm("fma.rn.f32x2 %0, %1, %2, %0;" : "+l"(acc) : "l"(s2), "l"(wv))

__device__ __forceinline__ float hsum16(float v) {
    v += __shfl_xor_sync(0xffffffffu, v, 1);
    v += __shfl_xor_sync(0xffffffffu, v, 2);
    v += __shfl_xor_sync(0xffffffffu, v, 4);
    v += __shfl_xor_sync(0xffffffffu, v, 8);
    return v;
}
__device__ __forceinline__ float hmax16(float v) {
    v = fmaxf(v, __shfl_xor_sync(0xffffffffu, v, 1));
    v = fmaxf(v, __shfl_xor_sync(0xffffffffu, v, 2));
    v = fmaxf(v, __shfl_xor_sync(0xffffffffu, v, 4));
    v = fmaxf(v, __shfl_xor_sync(0xffffffffu, v, 8));
    return v;
}

__global__ __launch_bounds__(NTHR, 2) void wda_kernel(
    const float* __restrict__ turb, const float* __restrict__ weath,
    const float* __restrict__ w_t,  const float* __restrict__ b_t,
    const float* __restrict__ w_w,  const float* __restrict__ b_w,
    const float* __restrict__ g_t,  const float* __restrict__ be_t,
    const float* __restrict__ g_w,  const float* __restrict__ be_w,
    const float* __restrict__ w_qkv,const float* __restrict__ b_qkv,
    const float* __restrict__ w_ao, const float* __restrict__ b_ao,
    const float* __restrict__ w_op, const float* __restrict__ b_op,
    float* __restrict__ out)
{
    extern __shared__ u32t smu[];
    float* smf = reinterpret_cast<float*>(smu);
    const int tid  = threadIdx.x;
    const int warp = tid >> 5, lane = tid & 31;
    const int hh   = lane >> 4;
    const int hh2  = hh * 2;
    const int et   = lane & 15;
    const int e4   = et * 4;
    const int et2  = et * 2;
    const size_t s = blockIdx.x;
    const float* turb_s  = turb  + s * (size_t)(NT * CM);
    const float* weath_s = weath + s * (size_t)(NW * CM);
    float*       out_s   = out   + s * (size_t)(NT * CM);

    for (int i = tid; i < 8 * 34; i += NTHR) smu[VU + 200 * 34 + i] = 0u;

    // ===== Stage 1: h = LN(x @ W^T + b); weights split XU(k<128)/MISC =====
#pragma unroll 1
    for (int src = 0; src < 2; ++src) {
        const float* inp = src ? weath_s : turb_s;
        const float* Wg  = src ? w_w  : w_t;
        const float* bg  = src ? b_w  : b_t;
        const float* gg  = src ? g_w  : g_t;
        const float* beg = src ? be_w : be_t;
        const int ngrp   = src ? 13 : 25;
        const int rmax   = src ? NW - 1 : NT - 1;
        u32t* hb = smu + (src ? KU : VU);
        const float4 bv = ld4(bg + e4), gv = ld4(gg + e4), ev = ld4(beg + e4);

        __syncthreads();
        for (int idx = tid; idx < 128 * 32; idx += NTHR) {
            const int c = idx & 127, j = idx >> 7;
            smu[XU + c * 34 + j] =
                packbf(Wg[(2 * j) * 256 + c], Wg[(2 * j + 1) * 256 + c]);
            smu[MISC + c * 34 + j] =
                packbf(Wg[(2 * j) * 256 + 128 + c], Wg[(2 * j + 1) * 256 + 128 + c]);
        }
        __syncthreads();
#pragma unroll 1
        for (int g = warp; g < ngrp; g += NWARP) {
            const int r0 = g * 8 + hh * 4;
            const float* xp0 = inp + (size_t)min(r0 + 0, rmax) * CM;
            const float* xp1 = inp + (size_t)min(r0 + 1, rmax) * CM;
            const float* xp2 = inp + (size_t)min(r0 + 2, rmax) * CM;
            const float* xp3 = inp + (size_t)min(r0 + 3, rmax) * CM;
            u64 ac[4][2] = {};
#pragma unroll 1
            for (int half = 0; half < 2; ++half) {
                const u32t* wbase = smu + (half ? MISC : XU);
                const int xo = half << 7;
#pragma unroll 2
                for (int k = 0; k < 128; k += 4) {
                    const float4 x0 = ld4(xp0 + xo + k), x1 = ld4(xp1 + xo + k);
                    const float4 x2 = ld4(xp2 + xo + k), x3 = ld4(xp3 + xo + k);
                    const u32t* wp = wbase + k * 34 + et2;
                    const uint2 c0 = ld2u(wp),      c1 = ld2u(wp + 34),
                                c2 = ld2u(wp + 68), c3 = ld2u(wp + 102);
                    const u64 w00 = bfpair(c0.x), w01 = bfpair(c0.y);
                    const u64 w10 = bfpair(c1.x), w11 = bfpair(c1.y);
                    const u64 w20 = bfpair(c2.x), w21 = bfpair(c2.y);
                    const u64 w30 = bfpair(c3.x), w31 = bfpair(c3.y);
#define S1ROW(i, xv) { \
                    u64 s_ = pk1((xv).x); FMA2(ac[i][0], s_, w00); FMA2(ac[i][1], s_, w01); \
                    s_ = pk1((xv).y);     FMA2(ac[i][0], s_, w10); FMA2(ac[i][1], s_, w11); \
                    s_ = pk1((xv).z);     FMA2(ac[i][0], s_, w20); FMA2(ac[i][1], s_, w21); \
                    s_ = pk1((xv).w);     FMA2(ac[i][0], s_, w30); FMA2(ac[i][1], s_, w31); }
                    S1ROW(0, x0) S1ROW(1, x1) S1ROW(2, x2) S1ROW(3, x3)
#undef S1ROW
                }
            }
#pragma unroll
            for (int i = 0; i < 4; ++i) {
                float y0, y1, y2, y3;
                upk(ac[i][0], y0, y1); upk(ac[i][1], y2, y3);
                y0 += bv.x; y1 += bv.y; y2 += bv.z; y3 += bv.w;
                const float mu = hsum16(y0 + y1 + y2 + y3) * 0.015625f;
                const float qq = hsum16(y0*y0 + y1*y1 + y2*y2 + y3*y3) * 0.015625f;
                const float rs = rsqrtf(qq - mu * mu + 1e-5f);
                y0 = (y0 - mu) * rs * gv.x + ev.x;
                y1 = (y1 - mu) * rs * gv.y + ev.y;
                y2 = (y2 - mu) * rs * gv.z + ev.z;
                y3 = (y3 - mu) * rs * gv.w + ev.w;
                uint2 hv; hv.x = packbf(y0, y1); hv.y = packbf(y2, y3);
                st2u(hb + (r0 + i) * 34 + et2, hv);
            }
        }
    }
    __syncthreads();

    // ===== Stage 2: cross-attention, x(bf16,XU) = softmax(h_t h_w^T/8) h_w =
    {
        float* pA = smf + MISC + warp * 448 + hh2 * 112;
        float* pB = pA + 112;
        int moff[7];
#pragma unroll
        for (int j = 0; j < 7; ++j)
            moff[j] = KU + min(et + 16 * j, NW - 1) * 34;
#pragma unroll 1
        for (int g = warp; g < NT / 4; g += NWARP) {
            const int rA = g * 4 + hh2;
            const u32t* qpa = smu + VU + rA * 34;
            const u32t* qpb = qpa + 34;
            u64 la[7] = {}, lb[7] = {};
#pragma unroll 4
            for (int dc = 0; dc < 32; dc += 2) {
                const uint2 qa = ld2u(qpa + dc), qb = ld2u(qpb + dc);
                const u64 qa0 = bfpair(qa.x), qa1 = bfpair(qa.y);
                const u64 qb0 = bfpair(qb.x), qb1 = bfpair(qb.y);
#pragma unroll
                for (int j = 0; j < 7; ++j) {
                    const uint2 kv = ld2u(smu + moff[j] + dc);
                    const u64 k0 = bfpair(kv.x), k1 = bfpair(kv.y);
                    FMA2(la[j], qa0, k0); FMA2(la[j], qa1, k1);
                    FMA2(lb[j], qb0, k0); FMA2(lb[j], qb1, k1);
                }
            }
            float lA[7], lB[7];
#pragma unroll
            for (int j = 0; j < 7; ++j) {
                float lo, hi;
                upk(la[j], lo, hi); lA[j] = lo + hi;
                upk(lb[j], lo, hi); lB[j] = lo + hi;
            }
            float mA = -1e30f, mB = -1e30f;
#pragma unroll
            for (int j = 0; j < 7; ++j) {
                const bool ok = et + 16 * j < NW;
                lA[j] = ok ? lA[j] * 0.125f : -1e30f;
                lB[j] = ok ? lB[j] * 0.125f : -1e30f;
                mA = fmaxf(mA, lA[j]); mB = fmaxf(mB, lB[j]);
            }
            mA = hmax16(mA); mB = hmax16(mB);
            float sA = 0.f, sB = 0.f;
#pragma unroll
            for (int j = 0; j < 7; ++j) {
                const bool ok = et + 16 * j < NW;
                lA[j] = ok ? __expf(lA[j] - mA) : 0.f;
                lB[j] = ok ? __expf(lB[j] - mB) : 0.f;
                sA += lA[j]; sB += lB[j];
            }
            const float iA = 1.f / hsum16(sA), iB = 1.f / hsum16(sB);
#pragma unroll
            for (int j = 0; j < 7; ++j) {
                const int m = et + 16 * j;
                if (m < NW) { pA[m] = lA[j] * iA; pB[m] = lB[j] * iB; }
            }
            __syncwarp();
            u64 c0A = 0, c1A = 0, c0B = 0, c1B = 0;
#pragma unroll 5
            for (int m = 0; m < NW; m += 4) {
                const float4 pa = ld4(pA + m), pb = ld4(pB + m);
                const u32t* kp = smu + KU + m * 34 + et2;
                const uint2 m0 = ld2u(kp),      m1 = ld2u(kp + 34),
                            m2 = ld2u(kp + 68), m3 = ld2u(kp + 102);
                const u64 w00 = bfpair(m0.x), w01 = bfpair(m0.y);
                const u64 w10 = bfpair(m1.x), w11 = bfpair(m1.y);
                const u64 w20 = bfpair(m2.x), w21 = bfpair(m2.y);
                const u64 w30 = bfpair(m3.x), w31 = bfpair(m3.y);
                u64 s_;
                s_ = pk1(pa.x); FMA2(c0A, s_, w00); FMA2(c1A, s_, w01);
                s_ = pk1(pa.y); FMA2(c0A, s_, w10); FMA2(c1A, s_, w11);
                s_ = pk1(pa.z); FMA2(c0A, s_, w20); FMA2(c1A, s_, w21);
                s_ = pk1(pa.w); FMA2(c0A, s_, w30); FMA2(c1A, s_, w31);
                s_ = pk1(pb.x); FMA2(c0B, s_, w00); FMA2(c1B, s_, w01);
                s_ = pk1(pb.y); FMA2(c0B, s_, w10); FMA2(c1B, s_, w11);
                s_ = pk1(pb.z); FMA2(c0B, s_, w20); FMA2(c1B, s_, w21);
                s_ = pk1(pb.w); FMA2(c0B, s_, w30); FMA2(c1B, s_, w31);
            }
            float t0, t1, t2, t3; uint2 pr;
            upk(c0A, t0, t1); upk(c1A, t2, t3);
            pr.x = packbf(t0, t1); pr.y = packbf(t2, t3);
            st2u(smu + XU + rA * 34 + et2, pr);
            upk(c0B, t0, t1); upk(c1B, t2, t3);
            pr.x = packbf(t0, t1); pr.y = packbf(t2, t3);
            st2u(smu + XU + (rA + 1) * 34 + et2, pr);
            __syncwarp();
        }
    }
    __syncthreads();

    // stage S3 weights into MISC [64][98]
    for (int idx = tid; idx < 64 * 96; idx += NTHR) {
        const int d = idx & 63, j = idx >> 6;
        smu[MISC + d * 98 + j] =
            packbf(w_qkv[(2 * j) * 64 + d], w_qkv[(2 * j + 1) * 64 + d]);
    }
    __syncthreads();

    // ===== Stage 3: QKV projection (x bf16 in XU; q overwrites x) ==========
    {
        const float4 bq0 = ld4(b_qkv + e4), bq1 = ld4(b_qkv + 64 + e4),
                     bq2 = ld4(b_qkv + 128 + e4);
#pragma unroll 1
        for (int g = warp; g < NT / 4; g += NWARP) {
            const int rA = g * 4 + hh2;
            const u32t* xuA = smu + XU + rA * 34;
            const u32t* xuB = xuA + 34;
            u64 q0A = pk2(bq0.x, bq0.y), q1A = pk2(bq0.z, bq0.w);
            u64 k0A = pk2(bq1.x, bq1.y), k1A = pk2(bq1.z, bq1.w);
            u64 v0A = pk2(bq2.x, bq2.y), v1A = pk2(bq2.z, bq2.w);
            u64 q0B = q0A, q1B = q1A, k0B = k0A, k1B = k1A, v0B = v0A, v1B = v1A;
#pragma unroll 4
            for (int d = 0; d < 64; d += 2) {
                const unsigned va = xuA[d >> 1], vb = xuB[d >> 1];
                const u32t* wp0 = smu + MISC + d * 98 + et2;
                const u32t* wp1 = wp0 + 98;
                const uint2 uq0 = ld2u(wp0), uk0 = ld2u(wp0 + 32), uv0 = ld2u(wp0 + 64);
                const uint2 uq1 = ld2u(wp1), uk1 = ld2u(wp1 + 32), uv1 = ld2u(wp1 + 64);
                u64 s_;
                s_ = bcastlo(va);
                FMA2(q0A, s_, bfpair(uq0.x)); FMA2(q1A, s_, bfpair(uq0.y));
                FMA2(k0A, s_, bfpair(uk0.x)); FMA2(k1A, s_, bfpair(uk0.y));
                FMA2(v0A, s_, bfpair(uv0.x)); FMA2(v1A, s_, bfpair(uv0.y));
                s_ = bcasthi(va);
                FMA2(q0A, s_, bfpair(uq1.x)); FMA2(q1A, s_, bfpair(uq1.y));
                FMA2(k0A, s_, bfpair(uk1.x)); FMA2(k1A, s_, bfpair(uk1.y));
                FMA2(v0A, s_, bfpair(uv1.x)); FMA2(v1A, s_, bfpair(uv1.y));
                s_ = bcastlo(vb);
                FMA2(q0B, s_, bfpair(uq0.x)); FMA2(q1B, s_, bfpair(uq0.y));
                FMA2(k0B, s_, bfpair(uk0.x)); FMA2(k1B, s_, bfpair(uk0.y));
                FMA2(v0B, s_, bfpair(uv0.x)); FMA2(v1B, s_, bfpair(uv0.y));
                s_ = bcasthi(vb);
                FMA2(q0B, s_, bfpair(uq1.x)); FMA2(q1B, s_, bfpair(uq1.y));
                FMA2(k0B, s_, bfpair(uk1.x)); FMA2(k1B, s_, bfpair(uk1.y));
                FMA2(v0B, s_, bfpair(uv1.x)); FMA2(v1B, s_, bfpair(uv1.y));
            }
            __syncwarp();   // all x reads done before q overwrites
            float t0, t1, t2, t3; uint2 pr;
#define STBF(base, row, h0, h1) { upk(h0, t0, t1); upk(h1, t2, t3); \
            pr.x = packbf(t0, t1); pr.y = packbf(t2, t3); \
            st2u(smu + (base) + (row) * 34 + et2, pr); }
            STBF(XU, rA, q0A, q1A) STBF(XU, rA + 1, q0B, q1B)
            STBF(KU, rA, k0A, k1A) STBF(KU, rA + 1, k0B, k1B)
            STBF(VU, rA, v0A, v1A) STBF(VU, rA + 1, v0B, v1B)
#undef STBF
        }
    }
    __syncthreads();

    // ===== Stage 4: 4-head self-attention (o bf16 overwrites q in XU) ======
    {
        float* pA = smf + MISC + warp * 832 + hh2 * 208;
        float* pB = pA + 208;
        const int ms = et >> 2;
        int koff[13];
#pragma unroll
        for (int j = 0; j < 13; ++j)
            koff[j] = KU + min(et + 16 * j, NT - 1) * 34;
#pragma unroll 1
        for (int g = warp; g < NT / 4; g += NWARP) {
            const int rA = g * 4 + hh2;
            if (et < 8) { pA[200 + et] = 0.f; pB[200 + et] = 0.f; }
#pragma unroll 1
            for (int hd0 = 0; hd0 < 64; hd0 += 16) {
                const int hc = hd0 >> 1;
                const u32t* squA = smu + XU + rA * 34 + hc;
                const u32t* squB = squA + 34;
                float lA[13], lB[13];
#pragma unroll
                for (int j = 0; j < 13; ++j) { lA[j] = 0.f; lB[j] = 0.f; }
#pragma unroll
                for (int d = 0; d < 16; d += 4) {
                    const uint2 qa = ld2u(squA + (d >> 1));
                    const uint2 qb = ld2u(squB + (d >> 1));
                    const float a0 = bflo(qa.x), a1 = bfhi(qa.x),
                                a2 = bflo(qa.y), a3 = bfhi(qa.y);
                    const float b0 = bflo(qb.x), b1 = bfhi(qb.x),
                                b2 = bflo(qb.y), b3 = bfhi(qb.y);
#pragma unroll
                    for (int j = 0; j < 13; ++j) {
                        const uint2 kv = ld2u(smu + koff[j] + hc + (d >> 1));
                        const float k0 = bflo(kv.x), k1 = bfhi(kv.x);
                        const float k2 = bflo(kv.y), k3 = bfhi(kv.y);
                        lA[j] = fmaf(a3, k3, fmaf(a2, k2,
                                fmaf(a1, k1, fmaf(a0, k0, lA[j]))));
                        lB[j] = fmaf(b3, k3, fmaf(b2, k2,
                                fmaf(b1, k1, fmaf(b0, k0, lB[j]))));
                    }
                }
                float mA = -1e30f, mB = -1e30f;
#pragma unroll
                for (int j = 0; j < 13; ++j) {
                    const bool ok = et + 16 * j < NT;
                    lA[j] = ok ? lA[j] * 0.25f : -1e30f;
                    lB[j] = ok ? lB[j] * 0.25f : -1e30f;
                    mA = fmaxf(mA, lA[j]); mB = fmaxf(mB, lB[j]);
                }
                mA = hmax16(mA); mB = hmax16(mB);
                float sA = 0.f, sB = 0.f;
#pragma unroll
                for (int j = 0; j < 13; ++j) {
                    const bool ok = et + 16 * j < NT;
                    lA[j] = ok ? __expf(lA[j] - mA) : 0.f;
                    lB[j] = ok ? __expf(lB[j] - mB) : 0.f;
                    sA += lA[j]; sB += lB[j];
                }
                const float iA = 1.f / hsum16(sA), iB = 1.f / hsum16(sB);
#pragma unroll
                for (int j = 0; j < 13; ++j) {
                    const int m = et + 16 * j;
                    if (m < NT) { pA[m] = lA[j] * iA; pB[m] = lB[j] * iB; }
                }
                __syncwarp();
                u64 o0A = 0, o1A = 0, o0B = 0, o1B = 0;
                const int m0 = ms * 52;
                const int vcol = hc + (et & 3) * 2;
#pragma unroll
                for (int mi = 0; mi < 52; mi += 4) {
                    const int m = m0 + mi;
                    const float4 pa = ld4(pA + m), pb = ld4(pB + m);
                    const u32t* vp = smu + VU + m * 34 + vcol;
                    const uint2 r0 = ld2u(vp),      r1 = ld2u(vp + 34),
                                r2 = ld2u(vp + 68), r3 = ld2u(vp + 102);
                    const u64 v00 = bfpair(r0.x), v01 = bfpair(r0.y);
                    const u64 v10 = bfpair(r1.x), v11 = bfpair(r1.y);
                    const u64 v20 = bfpair(r2.x), v21 = bfpair(r2.y);
                    const u64 v30 = bfpair(r3.x), v31 = bfpair(r3.y);
                    u64 s_;
                    s_ = pk1(pa.x); FMA2(o0A, s_, v00); FMA2(o1A, s_, v01);
                    s_ = pk1(pa.y); FMA2(o0A, s_, v10); FMA2(o1A, s_, v11);
                    s_ = pk1(pa.z); FMA2(o0A, s_, v20); FMA2(o1A, s_, v21);
                    s_ = pk1(pa.w); FMA2(o0A, s_, v30); FMA2(o1A, s_, v31);
                    s_ = pk1(pb.x); FMA2(o0B, s_, v00); FMA2(o1B, s_, v01);
                    s_ = pk1(pb.y); FMA2(o0B, s_, v10); FMA2(o1B, s_, v11);
                    s_ = pk1(pb.z); FMA2(o0B, s_, v20); FMA2(o1B, s_, v21);
                    s_ = pk1(pb.w); FMA2(o0B, s_, v30); FMA2(o1B, s_, v31);
                }
                float a0, a1, a2, a3, b0, b1, b2, b3;
                upk(o0A, a0, a1); upk(o1A, a2, a3);
                upk(o0B, b0, b1); upk(o1B, b2, b3);
#define RED48(c) { c += __shfl_xor_sync(0xffffffffu, c, 4); \
                   c += __shfl_xor_sync(0xffffffffu, c, 8); }
                RED48(a0) RED48(a1) RED48(a2) RED48(a3)
                RED48(b0) RED48(b1) RED48(b2) RED48(b3)
#undef RED48
                if (ms == 0) {
                    uint2 pr;
                    pr.x = packbf(a0, a1); pr.y = packbf(a2, a3);
                    st2u(smu + XU + rA * 34 + vcol, pr);
                    pr.x = packbf(b0, b1); pr.y = packbf(b2, b3);
                    st2u(smu + XU + (rA + 1) * 34 + vcol, pr);
                }
                __syncwarp();
            }
        }
    }
    __syncthreads();

    // stage S5 weights: aoW -> MISC [64][34]; opW -> KU [64][130] (K/V dead)
    for (int idx = tid; idx < 64 * 32; idx += NTHR) {
        const int d = idx & 63, j = idx >> 6;
        smu[MISC + d * 34 + j] =
            packbf(w_ao[(2 * j) * 64 + d], w_ao[(2 * j + 1) * 64 + d]);
    }
    for (int idx = tid; idx < 64 * 128; idx += NTHR) {
        const int e = idx & 63, j = idx >> 6;
        smu[KU + e * 130 + j] =
            packbf(w_op[(2 * j) * 64 + e], w_op[(2 * j + 1) * 64 + e]);
    }
    __syncthreads();

    // ===== Stage 5: A = o@aoT + b_ao; out = turb + A@opT + b_op ===========
    {
        const float4 bao  = ld4(b_ao + e4);
        const float4 bop0 = ld4(b_op + e4),       bop1 = ld4(b_op + 64 + e4),
                     bop2 = ld4(b_op + 128 + e4), bop3 = ld4(b_op + 192 + e4);
        u32t* Abuf = smu + ABF + warp * 136;
#pragma unroll 1
        for (int g = warp; g < NT / 4; g += NWARP) {
            const int rA = g * 4 + hh2;
            const u32t* orA = smu + XU + rA * 34;
            const u32t* orB = orA + 34;
            u64 a0A = pk2(bao.x, bao.y), a1A = pk2(bao.z, bao.w);
            u64 a0B = a0A, a1B = a1A;
#pragma unroll 4
            for (int d = 0; d < 64; d += 2) {
                const unsigned va = orA[d >> 1], vb = orB[d >> 1];
                const u32t* wp0 = smu + MISC + d * 34 + et2;
                const uint2 u0 = ld2u(wp0), u1 = ld2u(wp0 + 34);
                const u64 w00 = bfpair(u0.x), w01 = bfpair(u0.y);
                const u64 w10 = bfpair(u1.x), w11 = bfpair(u1.y);
                u64 s_;
                s_ = bcastlo(va); FMA2(a0A, s_, w00); FMA2(a1A, s_, w01);
                s_ = bcasthi(va); FMA2(a0A, s_, w10); FMA2(a1A, s_, w11);
                s_ = bcastlo(vb); FMA2(a0B, s_, w00); FMA2(a1B, s_, w01);
                s_ = bcasthi(vb); FMA2(a0B, s_, w10); FMA2(a1B, s_, w11);
            }
            float t0, t1, t2, t3; uint2 pr;
            upk(a0A, t0, t1); upk(a1A, t2, t3);
            pr.x = packbf(t0, t1); pr.y = packbf(t2, t3);
            st2u(Abuf + hh2 * 34 + et2, pr);
            upk(a0B, t0, t1); upk(a1B, t2, t3);
            pr.x = packbf(t0, t1); pr.y = packbf(t2, t3);
            st2u(Abuf + (hh2 + 1) * 34 + et2, pr);
            __syncwarp();
            const float* tA = turb_s + (size_t)rA * CM;
            const float* tB = tA + CM;
            float* outA = out_s + (size_t)rA * CM;
            float* outB = outA + CM;
            u64 aA[8], aB[8];
            {
                float4 r;
                r = ld4(tA + e4);
                aA[0] = pk2(bop0.x + r.x, bop0.y + r.y); aA[1] = pk2(bop0.z + r.z, bop0.w + r.w);
                r = ld4(tA + 64 + e4);
                aA[2] = pk2(bop1.x + r.x, bop1.y + r.y); aA[3] = pk2(bop1.z + r.z, bop1.w + r.w);
                r = ld4(tA + 128 + e4);
                aA[4] = pk2(bop2.x + r.x, bop2.y + r.y); aA[5] = pk2(bop2.z + r.z, bop2.w + r.w);
                r = ld4(tA + 192 + e4);
                aA[6] = pk2(bop3.x + r.x, bop3.y + r.y); aA[7] = pk2(bop3.z + r.z, bop3.w + r.w);
                r = ld4(tB + e4);
                aB[0] = pk2(bop0.x + r.x, bop0.y + r.y); aB[1] = pk2(bop0.z + r.z, bop0.w + r.w);
                r = ld4(tB + 64 + e4);
                aB[2] = pk2(bop1.x + r.x, bop1.y + r.y); aB[3] = pk2(bop1.z + r.z, bop1.w + r.w);
                r = ld4(tB + 128 + e4);
                aB[4] = pk2(bop2.x + r.x, bop2.y + r.y); aB[5] = pk2(bop2.z + r.z, bop2.w + r.w);
                r = ld4(tB + 192 + e4);
                aB[6] = pk2(bop3.x + r.x, bop3.y + r.y); aB[7] = pk2(bop3.z + r.z, bop3.w + r.w);
            }
            const u32t* arA = Abuf + hh2 * 34;
            const u32t* arB = arA + 34;
#pragma unroll 4
            for (int e = 0; e < 64; e += 2) {
                const unsigned ua = arA[e >> 1], ub = arB[e >> 1];
                const u32t* wp0 = smu + KU + e * 130 + et2;
                const u32t* wp1 = wp0 + 130;
#define OPH(wp, sa_, sb_) { \
                const uint2 u0 = ld2u(wp),      u1 = ld2u((wp) + 32), \
                            u2 = ld2u((wp) + 64), u3 = ld2u((wp) + 96); \
                const u64 w00 = bfpair(u0.x), w01 = bfpair(u0.y); \
                const u64 w10 = bfpair(u1.x), w11 = bfpair(u1.y); \
                const u64 w20 = bfpair(u2.x), w21 = bfpair(u2.y); \
                const u64 w30 = bfpair(u3.x), w31 = bfpair(u3.y); \
                FMA2(aA[0], sa_, w00); FMA2(aA[1], sa_, w01); \
                FMA2(aA[2], sa_, w10); FMA2(aA[3], sa_, w11); \
                FMA2(aA[4], sa_, w20); FMA2(aA[5], sa_, w21); \
                FMA2(aA[6], sa_, w30); FMA2(aA[7], sa_, w31); \
                FMA2(aB[0], sb_, w00); FMA2(aB[1], sb_, w01); \
                FMA2(aB[2], sb_, w10); FMA2(aB[3], sb_, w11); \
                FMA2(aB[4], sb_, w20); FMA2(aB[5], sb_, w21); \
                FMA2(aB[6], sb_, w30); FMA2(aB[7], sb_, w31); }
                OPH(wp0, bcastlo(ua), bcastlo(ub))
                OPH(wp1, bcasthi(ua), bcasthi(ub))
#undef OPH
            }
            st4f(outA + e4,       aA[0], aA[1]); st4f(outA + 64 + e4,  aA[2], aA[3]);
            st4f(outA + 128 + e4, aA[4], aA[5]); st4f(outA + 192 + e4, aA[6], aA[7]);
            st4f(outB + e4,       aB[0], aB[1]); st4f(outB + 64 + e4,  aB[2], aB[3]);
            st4f(outB + 128 + e4, aB[4], aB[5]); st4f(outB + 192 + e4, aB[6], aB[7]);
            __syncwarp();
        }
    }
}

extern "C" void kernel_launch(void* const* d_in, const int* in_sizes, int n_in,
                              void* d_out, int out_size)
{
    const float* turb  = (const float*)d_in[0];
    const float* weath = (const float*)d_in[1];
    const float* w_t   = (const float*)d_in[2];
    const float* b_t   = (const float*)d_in[3];
    const float* w_w   = (const float*)d_in[4];
    const float* b_w   = (const float*)d_in[5];
    const float* g_t   = (const float*)d_in[6];
    const float* be_t  = (const float*)d_in[7];
    const float* g_w   = (const float*)d_in[8];
    const float* be_w  = (const float*)d_in[9];
    const float* w_qkv = (const float*)d_in[10];
    const float* b_qkv = (const float*)d_in[11];
    const float* w_ao  = (const float*)d_in[12];
    const float* b_ao  = (const float*)d_in[13];
    const float* w_op  = (const float*)d_in[14];
    const float* b_op  = (const float*)d_in[15];
    float* out = (float*)d_out;

    const int S = in_sizes[0] / (NT * CM);   // 768
    const size_t smem = (size_t)SMEM_U * sizeof(unsigned);
    cudaFuncSetAttribute(wda_kernel, cudaFuncAttributeMaxDynamicSharedMemorySize,
                         (int)smem);
    wda_kernel<<<S, NTHR, smem>>>(turb, weath, w_t, b_t, w_w, b_w,
                                  g_t, be_t, g_w, be_w, w_qkv, b_qkv,
                                  w_ao, b_ao, w_op, b_op, out);
}

// round 10
// speedup vs baseline: 1.5868x; 1.5160x over previous
#include <cuda_runtime.h>

// Round 10 (= Round 9 design, hb offset fix): mma.sync bf16 HMMA for stages
// 1/3/5; scalar stages 2/4 kept. 256 thr, 2 CTAs/SM. smem 113152 B.

constexpr int NTHR = 256;
constexpr int NWARP = 8;
constexpr int NT = 200, NW = 100, CM = 256;

// u32 offsets
constexpr int XU   = 0;              // [208][36] x/q/o bf16 pairs; S1 A-staging
constexpr int KU   = 7488;           // [208][34] h_w/K ; S5: w_op half0 [128][36]
constexpr int VU   = 14560;          // [208][34] h_t/V ; S5: w_op half1 [128][36]
constexpr int MISC = 21632;          // 6656: B-staging / probs
constexpr int SMEM_U = 28288;        // 113152 bytes

typedef unsigned long long u64;
typedef unsigned u32t;

__device__ __forceinline__ float4 ld4(const float* p) {
    return *reinterpret_cast<const float4*>(p);
}
__device__ __forceinline__ uint2 ld2u(const u32t* p) {
    return *reinterpret_cast<const uint2*>(p);
}
__device__ __forceinline__ void st2u(u32t* p, const uint2 v) {
    *reinterpret_cast<uint2*>(p) = v;
}
__device__ __forceinline__ u64 pk1(float s) {
    u64 r; unsigned u = __float_as_uint(s);
    asm("mov.b64 %0, {%1, %1};" : "=l"(r) : "r"(u));
    return r;
}
__device__ __forceinline__ void upk(u64 v, float& lo, float& hi) {
    unsigned a, b;
    asm("mov.b64 {%0, %1}, %2;" : "=r"(a), "=r"(b) : "l"(v));
    lo = __uint_as_float(a); hi = __uint_as_float(b);
}
__device__ __forceinline__ u64 bfpair(unsigned v) {
    unsigned lo = v << 16, hi = v & 0xffff0000u;
    u64 r;
    asm("mov.b64 %0, {%1, %2};" : "=l"(r) : "r"(lo), "r"(hi));
    return r;
}
__device__ __forceinline__ float bflo(unsigned v) { return __uint_as_float(v << 16); }
__device__ __forceinline__ float bfhi(unsigned v) { return __uint_as_float(v & 0xffff0000u); }
__device__ __forceinline__ unsigned packbf(float lo, float hi) {
    unsigned r;
    asm("cvt.rn.bf16x2.f32 %0, %1, %2;" : "=r"(r) : "f"(hi), "f"(lo));
    return r;
}
#define FMA2(acc, s2, wv) \
    asm("fma.rn.f32x2 %0, %1, %2, %0;" : "+l"(acc) : "l"(s2), "l"(wv))

__device__ __forceinline__ void mma16816(float* d, const unsigned* a,
                                         unsigned b0, unsigned b1) {
    asm volatile(
        "mma.sync.aligned.m16n8k16.row.col.f32.bf16.bf16.f32 "
        "{%0,%1,%2,%3}, {%4,%5,%6,%7}, {%8,%9}, {%0,%1,%2,%3};"
        : "+f"(d[0]), "+f"(d[1]), "+f"(d[2]), "+f"(d[3])
        : "r"(a[0]), "r"(a[1]), "r"(a[2]), "r"(a[3]), "r"(b0), "r"(b1));
}

__device__ __forceinline__ float hsum16(float v) {
    v += __shfl_xor_sync(0xffffffffu, v, 1);
    v += __shfl_xor_sync(0xffffffffu, v, 2);
    v += __shfl_xor_sync(0xffffffffu, v, 4);
    v += __shfl_xor_sync(0xffffffffu, v, 8);
    return v;
}
__device__ __forceinline__ float hmax16(float v) {
    v = fmaxf(v, __shfl_xor_sync(0xffffffffu, v, 1));
    v = fmaxf(v, __shfl_xor_sync(0xffffffffu, v, 2));
    v = fmaxf(v, __shfl_xor_sync(0xffffffffu, v, 4));
    v = fmaxf(v, __shfl_xor_sync(0xffffffffu, v, 8));
    return v;
}

__global__ __launch_bounds__(NTHR, 2) void wda_kernel(
    const float* __restrict__ turb, const float* __restrict__ weath,
    const float* __restrict__ w_t,  const float* __restrict__ b_t,
    const float* __restrict__ w_w,  const float* __restrict__ b_w,
    const float* __restrict__ g_t,  const float* __restrict__ be_t,
    const float* __restrict__ g_w,  const float* __restrict__ be_w,
    const float* __restrict__ w_qkv,const float* __restrict__ b_qkv,
    const float* __restrict__ w_ao, const float* __restrict__ b_ao,
    const float* __restrict__ w_op, const float* __restrict__ b_op,
    float* __restrict__ out)
{
    extern __shared__ u32t smu[];
    float* smf = reinterpret_cast<float*>(smu);
    const int tid  = threadIdx.x;
    const int warp = tid >> 5, lane = tid & 31;
    const int hh   = lane >> 4;
    const int hh2  = hh * 2;
    const int et   = lane & 15;
    const int et2  = et * 2;
    const int g    = lane >> 2, tg = lane & 3;   // MMA fragment coords
    const size_t s = blockIdx.x;
    const float* turb_s  = turb  + s * (size_t)(NT * CM);
    const float* weath_s = weath + s * (size_t)(NW * CM);
    float*       out_s   = out   + s * (size_t)(NT * CM);

    for (int i = tid; i < 8 * 34; i += NTHR) smu[VU + 200 * 34 + i] = 0u;

    // ===== Stage 1 (MMA): h = LN(x @ W^T + b) -> h_t in VU, h_w in KU =====
#pragma unroll 1
    for (int src = 0; src < 2; ++src) {
        const float* inp = src ? weath_s : turb_s;
        const float* Wg  = src ? w_w  : w_t;
        const float* bg  = src ? b_w  : b_t;
        const float* gg  = src ? g_w  : g_t;
        const float* beg = src ? be_w : be_t;
        const int rows   = src ? NW : NT;
        const int nT     = src ? 7 : 13;
        const int rstage = nT * 16;
        const int hb     = src ? KU : VU;
        float acc[2][32];
#pragma unroll
        for (int i = 0; i < 2; ++i)
#pragma unroll
            for (int j = 0; j < 32; ++j) acc[i][j] = 0.f;

#pragma unroll 1
        for (int kc = 0; kc < 4; ++kc) {
            __syncthreads();
            for (int idx = tid; idx < rstage * 32; idx += NTHR) {
                const int r = idx >> 5, j = idx & 31;
                const int rr = min(r, rows - 1);
                const float2 v = *reinterpret_cast<const float2*>(
                    inp + (size_t)rr * CM + kc * 64 + 2 * j);
                smu[XU + r * 36 + j] = packbf(v.x, v.y);
            }
            for (int idx = tid; idx < 64 * 32; idx += NTHR) {
                const int d = idx >> 5, j = idx & 31;
                const float2 v = *reinterpret_cast<const float2*>(
                    Wg + d * 256 + kc * 64 + 2 * j);
                smu[MISC + d * 36 + j] = packbf(v.x, v.y);
            }
            __syncthreads();
#pragma unroll
            for (int tt = 0; tt < 2; ++tt) {
                const int ti = warp + tt * 8;
                if (ti < nT) {
#pragma unroll
                    for (int ks = 0; ks < 4; ++ks) {
                        unsigned af[4];
                        const int ar = XU + (ti * 16 + g) * 36 + ks * 8 + tg;
                        af[0] = smu[ar];     af[1] = smu[ar + 288];
                        af[2] = smu[ar + 4]; af[3] = smu[ar + 292];
#pragma unroll
                        for (int nt = 0; nt < 8; ++nt) {
                            const int br = MISC + (nt * 8 + g) * 36 + ks * 8 + tg;
                            mma16816(&acc[tt][nt * 4], af, smu[br], smu[br + 4]);
                        }
                    }
                }
            }
        }
        // bias + LN + store
#pragma unroll
        for (int tt = 0; tt < 2; ++tt) {
            const int ti = warp + tt * 8;
            if (ti < nT) {
                float s0 = 0.f, q0 = 0.f, s1 = 0.f, q1 = 0.f;
#pragma unroll
                for (int nt = 0; nt < 8; ++nt) {
                    const float2 bb = *reinterpret_cast<const float2*>(
                        bg + nt * 8 + 2 * tg);
                    float* a = &acc[tt][nt * 4];
                    a[0] += bb.x; a[1] += bb.y; a[2] += bb.x; a[3] += bb.y;
                    s0 += a[0] + a[1]; q0 += a[0]*a[0] + a[1]*a[1];
                    s1 += a[2] + a[3]; q1 += a[2]*a[2] + a[3]*a[3];
                }
#pragma unroll
                for (int o = 1; o <= 2; o <<= 1) {
                    s0 += __shfl_xor_sync(0xffffffffu, s0, o);
                    q0 += __shfl_xor_sync(0xffffffffu, q0, o);
                    s1 += __shfl_xor_sync(0xffffffffu, s1, o);
                    q1 += __shfl_xor_sync(0xffffffffu, q1, o);
                }
                const float mu0 = s0 * 0.015625f, mu1 = s1 * 0.015625f;
                const float rs0 = rsqrtf(q0 * 0.015625f - mu0 * mu0 + 1e-5f);
                const float rs1 = rsqrtf(q1 * 0.015625f - mu1 * mu1 + 1e-5f);
                const int r0 = ti * 16 + g, r1 = r0 + 8;
#pragma unroll
                for (int nt = 0; nt < 8; ++nt) {
                    const float2 gm = *reinterpret_cast<const float2*>(
                        gg + nt * 8 + 2 * tg);
                    const float2 be = *reinterpret_cast<const float2*>(
                        beg + nt * 8 + 2 * tg);
                    const float* a = &acc[tt][nt * 4];
                    if (r0 < rows)
                        smu[hb + r0 * 34 + nt * 4 + tg] =
                            packbf((a[0]-mu0)*rs0*gm.x + be.x,
                                   (a[1]-mu0)*rs0*gm.y + be.y);
                    if (r1 < rows)
                        smu[hb + r1 * 34 + nt * 4 + tg] =
                            packbf((a[2]-mu1)*rs1*gm.x + be.x,
                                   (a[3]-mu1)*rs1*gm.y + be.y);
                }
            }
        }
    }
    __syncthreads();

    // ===== Stage 2 (scalar): x(bf16->XU/36) = softmax(h_t h_w^T/8) h_w ====
    {
        float* pA = smf + MISC + warp * 448 + hh2 * 112;
        float* pB = pA + 112;
        int moff[7];
#pragma unroll
        for (int j = 0; j < 7; ++j)
            moff[j] = KU + min(et + 16 * j, NW - 1) * 34;
#pragma unroll 1
        for (int gg2 = warp; gg2 < NT / 4; gg2 += NWARP) {
            const int rA = gg2 * 4 + hh2;
            const u32t* qpa = smu + VU + rA * 34;
            const u32t* qpb = qpa + 34;
            u64 la[7] = {}, lb[7] = {};
#pragma unroll 4
            for (int dc = 0; dc < 32; dc += 2) {
                const uint2 qa = ld2u(qpa + dc), qb = ld2u(qpb + dc);
                const u64 qa0 = bfpair(qa.x), qa1 = bfpair(qa.y);
                const u64 qb0 = bfpair(qb.x), qb1 = bfpair(qb.y);
#pragma unroll
                for (int j = 0; j < 7; ++j) {
                    const uint2 kv = ld2u(smu + moff[j] + dc);
                    const u64 k0 = bfpair(kv.x), k1 = bfpair(kv.y);
                    FMA2(la[j], qa0, k0); FMA2(la[j], qa1, k1);
                    FMA2(lb[j], qb0, k0); FMA2(lb[j], qb1, k1);
                }
            }
            float lA[7], lB[7];
#pragma unroll
            for (int j = 0; j < 7; ++j) {
                float lo, hi;
                upk(la[j], lo, hi); lA[j] = lo + hi;
                upk(lb[j], lo, hi); lB[j] = lo + hi;
            }
            float mA = -1e30f, mB = -1e30f;
#pragma unroll
            for (int j = 0; j < 7; ++j) {
                const bool ok = et + 16 * j < NW;
                lA[j] = ok ? lA[j] * 0.125f : -1e30f;
                lB[j] = ok ? lB[j] * 0.125f : -1e30f;
                mA = fmaxf(mA, lA[j]); mB = fmaxf(mB, lB[j]);
            }
            mA = hmax16(mA); mB = hmax16(mB);
            float sA = 0.f, sB = 0.f;
#pragma unroll
            for (int j = 0; j < 7; ++j) {
                const bool ok = et + 16 * j < NW;
                lA[j] = ok ? __expf(lA[j] - mA) : 0.f;
                lB[j] = ok ? __expf(lB[j] - mB) : 0.f;
                sA += lA[j]; sB += lB[j];
            }
            const float iA = 1.f / hsum16(sA), iB = 1.f / hsum16(sB);
#pragma unroll
            for (int j = 0; j < 7; ++j) {
                const int m = et + 16 * j;
                if (m < NW) { pA[m] = lA[j] * iA; pB[m] = lB[j] * iB; }
            }
            __syncwarp();
            u64 c0A = 0, c1A = 0, c0B = 0, c1B = 0;
#pragma unroll 5
            for (int m = 0; m < NW; m += 4) {
                const float4 pa = ld4(pA + m), pb = ld4(pB + m);
                const u32t* kp = smu + KU + m * 34 + et2;
                const uint2 m0 = ld2u(kp),      m1 = ld2u(kp + 34),
                            m2 = ld2u(kp + 68), m3 = ld2u(kp + 102);
                const u64 w00 = bfpair(m0.x), w01 = bfpair(m0.y);
                const u64 w10 = bfpair(m1.x), w11 = bfpair(m1.y);
                const u64 w20 = bfpair(m2.x), w21 = bfpair(m2.y);
                const u64 w30 = bfpair(m3.x), w31 = bfpair(m3.y);
                u64 s_;
                s_ = pk1(pa.x); FMA2(c0A, s_, w00); FMA2(c1A, s_, w01);
                s_ = pk1(pa.y); FMA2(c0A, s_, w10); FMA2(c1A, s_, w11);
                s_ = pk1(pa.z); FMA2(c0A, s_, w20); FMA2(c1A, s_, w21);
                s_ = pk1(pa.w); FMA2(c0A, s_, w30); FMA2(c1A, s_, w31);
                s_ = pk1(pb.x); FMA2(c0B, s_, w00); FMA2(c1B, s_, w01);
                s_ = pk1(pb.y); FMA2(c0B, s_, w10); FMA2(c1B, s_, w11);
                s_ = pk1(pb.z); FMA2(c0B, s_, w20); FMA2(c1B, s_, w21);
                s_ = pk1(pb.w); FMA2(c0B, s_, w30); FMA2(c1B, s_, w31);
            }
            float t0, t1, t2, t3; uint2 pr;
            upk(c0A, t0, t1); upk(c1A, t2, t3);
            pr.x = packbf(t0, t1); pr.y = packbf(t2, t3);
            st2u(smu + XU + rA * 36 + et2, pr);
            upk(c0B, t0, t1); upk(c1B, t2, t3);
            pr.x = packbf(t0, t1); pr.y = packbf(t2, t3);
            st2u(smu + XU + (rA + 1) * 36 + et2, pr);
            __syncwarp();
        }
    }

    // ===== Stage 3 (MMA): qkv = x @ Wqkv^T + b; half0: k,v; half1: q ======
#pragma unroll 1
    for (int h = 0; h < 2; ++h) {
        __syncthreads();
        const int nbase = h ? 0 : 64;
        const int ncols = h ? 64 : 128;
        for (int idx = tid; idx < ncols * 32; idx += NTHR) {
            const int d = idx >> 5, j = idx & 31;
            const float2 v = *reinterpret_cast<const float2*>(
                w_qkv + (nbase + d) * 64 + 2 * j);
            smu[MISC + d * 36 + j] = packbf(v.x, v.y);
        }
        __syncthreads();
#pragma unroll
        for (int tt = 0; tt < 2; ++tt) {
            const int ti = warp + tt * 8;
            if (ti < 13) {
                unsigned af[16];
#pragma unroll
                for (int ks = 0; ks < 4; ++ks) {
                    const int ar = XU + (ti * 16 + g) * 36 + ks * 8 + tg;
                    af[ks*4+0] = smu[ar];     af[ks*4+1] = smu[ar + 288];
                    af[ks*4+2] = smu[ar + 4]; af[ks*4+3] = smu[ar + 292];
                }
                const int r0 = ti * 16 + g, r1 = r0 + 8;
                if (h == 0) {
                    float acc[16][4];
#pragma unroll
                    for (int nt = 0; nt < 16; ++nt)
#pragma unroll
                        for (int i = 0; i < 4; ++i) acc[nt][i] = 0.f;
#pragma unroll
                    for (int ks = 0; ks < 4; ++ks)
#pragma unroll
                        for (int nt = 0; nt < 16; ++nt) {
                            const int br = MISC + (nt * 8 + g) * 36 + ks * 8 + tg;
                            mma16816(acc[nt], &af[ks * 4], smu[br], smu[br + 4]);
                        }
#pragma unroll
                    for (int nt = 0; nt < 16; ++nt) {
                        const int n0 = 64 + nt * 8 + 2 * tg;
                        const float2 bb = *reinterpret_cast<const float2*>(b_qkv + n0);
                        const int base = (nt < 8) ? KU : VU;
                        const int cc = (nt & 7) * 4 + tg;
                        if (r0 < NT)
                            smu[base + r0 * 34 + cc] =
                                packbf(acc[nt][0] + bb.x, acc[nt][1] + bb.y);
                        if (r1 < NT)
                            smu[base + r1 * 34 + cc] =
                                packbf(acc[nt][2] + bb.x, acc[nt][3] + bb.y);
                    }
                } else {
                    float acc[8][4];
#pragma unroll
                    for (int nt = 0; nt < 8; ++nt)
#pragma unroll
                        for (int i = 0; i < 4; ++i) acc[nt][i] = 0.f;
#pragma unroll
                    for (int ks = 0; ks < 4; ++ks)
#pragma unroll
                        for (int nt = 0; nt < 8; ++nt) {
                            const int br = MISC + (nt * 8 + g) * 36 + ks * 8 + tg;
                            mma16816(acc[nt], &af[ks * 4], smu[br], smu[br + 4]);
                        }
#pragma unroll
                    for (int nt = 0; nt < 8; ++nt) {
                        const int n0 = nt * 8 + 2 * tg;
                        const float2 bb = *reinterpret_cast<const float2*>(b_qkv + n0);
                        const int cc = nt * 4 + tg;
                        if (r0 < NT)
                            smu[XU + r0 * 36 + cc] =
                                packbf(acc[nt][0] + bb.x, acc[nt][1] + bb.y);
                        if (r1 < NT)
                            smu[XU + r1 * 36 + cc] =
                                packbf(acc[nt][2] + bb.x, acc[nt][3] + bb.y);
                    }
                }
            }
        }
    }
    __syncthreads();

    // ===== Stage 4 (scalar): 4-head self-attn; o(bf16) overwrites q in XU ==
    {
        float* pA = smf + MISC + warp * 832 + hh2 * 208;
        float* pB = pA + 208;
        const int ms = et >> 2;
        int koff[13];
#pragma unroll
        for (int j = 0; j < 13; ++j)
            koff[j] = KU + min(et + 16 * j, NT - 1) * 34;
#pragma unroll 1
        for (int gg2 = warp; gg2 < NT / 4; gg2 += NWARP) {
            const int rA = gg2 * 4 + hh2;
            if (et < 8) { pA[200 + et] = 0.f; pB[200 + et] = 0.f; }
#pragma unroll 1
            for (int hd0 = 0; hd0 < 64; hd0 += 16) {
                const int hc = hd0 >> 1;
                const u32t* squA = smu + XU + rA * 36 + hc;
                const u32t* squB = squA + 36;
                float lA[13], lB[13];
#pragma unroll
                for (int j = 0; j < 13; ++j) { lA[j] = 0.f; lB[j] = 0.f; }
#pragma unroll
                for (int d = 0; d < 16; d += 4) {
                    const uint2 qa = ld2u(squA + (d >> 1));
                    const uint2 qb = ld2u(squB + (d >> 1));
                    const float a0 = bflo(qa.x), a1 = bfhi(qa.x),
                                a2 = bflo(qa.y), a3 = bfhi(qa.y);
                    const float b0 = bflo(qb.x), b1 = bfhi(qb.x),
                                b2 = bflo(qb.y), b3 = bfhi(qb.y);
#pragma unroll
                    for (int j = 0; j < 13; ++j) {
                        const uint2 kv = ld2u(smu + koff[j] + hc + (d >> 1));
                        const float k0 = bflo(kv.x), k1 = bfhi(kv.x);
                        const float k2 = bflo(kv.y), k3 = bfhi(kv.y);
                        lA[j] = fmaf(a3, k3, fmaf(a2, k2,
                                fmaf(a1, k1, fmaf(a0, k0, lA[j]))));
                        lB[j] = fmaf(b3, k3, fmaf(b2, k2,
                                fmaf(b1, k1, fmaf(b0, k0, lB[j]))));
                    }
                }
                float mA = -1e30f, mB = -1e30f;
#pragma unroll
                for (int j = 0; j < 13; ++j) {
                    const bool ok = et + 16 * j < NT;
                    lA[j] = ok ? lA[j] * 0.25f : -1e30f;
                    lB[j] = ok ? lB[j] * 0.25f : -1e30f;
                    mA = fmaxf(mA, lA[j]); mB = fmaxf(mB, lB[j]);
                }
                mA = hmax16(mA); mB = hmax16(mB);
                float sA = 0.f, sB = 0.f;
#pragma unroll
                for (int j = 0; j < 13; ++j) {
                    const bool ok = et + 16 * j < NT;
                    lA[j] = ok ? __expf(lA[j] - mA) : 0.f;
                    lB[j] = ok ? __expf(lB[j] - mB) : 0.f;
                    sA += lA[j]; sB += lB[j];
                }
                const float iA = 1.f / hsum16(sA), iB = 1.f / hsum16(sB);
#pragma unroll
                for (int j = 0; j < 13; ++j) {
                    const int m = et + 16 * j;
                    if (m < NT) { pA[m] = lA[j] * iA; pB[m] = lB[j] * iB; }
                }
                __syncwarp();
                u64 o0A = 0, o1A = 0, o0B = 0, o1B = 0;
                const int m0 = ms * 52;
                const int vcol = hc + (et & 3) * 2;
#pragma unroll
                for (int mi = 0; mi < 52; mi += 4) {
                    const int m = m0 + mi;
                    const float4 pa = ld4(pA + m), pb = ld4(pB + m);
                    const u32t* vp = smu + VU + m * 34 + vcol;
                    const uint2 r0 = ld2u(vp),      r1 = ld2u(vp + 34),
                                r2 = ld2u(vp + 68), r3 = ld2u(vp + 102);
                    const u64 v00 = bfpair(r0.x), v01 = bfpair(r0.y);
                    const u64 v10 = bfpair(r1.x), v11 = bfpair(r1.y);
                    const u64 v20 = bfpair(r2.x), v21 = bfpair(r2.y);
                    const u64 v30 = bfpair(r3.x), v31 = bfpair(r3.y);
                    u64 s_;
                    s_ = pk1(pa.x); FMA2(o0A, s_, v00); FMA2(o1A, s_, v01);
                    s_ = pk1(pa.y); FMA2(o0A, s_, v10); FMA2(o1A, s_, v11);
                    s_ = pk1(pa.z); FMA2(o0A, s_, v20); FMA2(o1A, s_, v21);
                    s_ = pk1(pa.w); FMA2(o0A, s_, v30); FMA2(o1A, s_, v31);
                    s_ = pk1(pb.x); FMA2(o0B, s_, v00); FMA2(o1B, s_, v01);
                    s_ = pk1(pb.y); FMA2(o0B, s_, v10); FMA2(o1B, s_, v11);
                    s_ = pk1(pb.z); FMA2(o0B, s_, v20); FMA2(o1B, s_, v21);
                    s_ = pk1(pb.w); FMA2(o0B, s_, v30); FMA2(o1B, s_, v31);
                }
                float a0, a1, a2, a3, b0, b1, b2, b3;
                upk(o0A, a0, a1); upk(o1A, a2, a3);
                upk(o0B, b0, b1); upk(o1B, b2, b3);
#define RED48(c) { c += __shfl_xor_sync(0xffffffffu, c, 4); \
                   c += __shfl_xor_sync(0xffffffffu, c, 8); }
                RED48(a0) RED48(a1) RED48(a2) RED48(a3)
                RED48(b0) RED48(b1) RED48(b2) RED48(b3)
#undef RED48
                if (ms == 0) {
                    uint2 pr;
                    pr.x = packbf(a0, a1); pr.y = packbf(a2, a3);
                    st2u(smu + XU + rA * 36 + vcol, pr);
                    pr.x = packbf(b0, b1); pr.y = packbf(b2, b3);
                    st2u(smu + XU + (rA + 1) * 36 + vcol, pr);
                }
                __syncwarp();
            }
        }
    }
    __syncthreads();

    // ===== Stage 5 (MMA): A1 = o@aoT + b_ao; out = turb + A1@opT + b_op ===
    for (int idx = tid; idx < 64 * 32; idx += NTHR) {
        const int d = idx >> 5, j = idx & 31;
        const float2 v = *reinterpret_cast<const float2*>(w_ao + d * 64 + 2 * j);
        smu[MISC + d * 36 + j] = packbf(v.x, v.y);
    }
    for (int idx = tid; idx < 128 * 32; idx += NTHR) {
        const int d = idx >> 5, j = idx & 31;
        const float2 v0 = *reinterpret_cast<const float2*>(w_op + d * 64 + 2 * j);
        smu[KU + d * 36 + j] = packbf(v0.x, v0.y);
        const float2 v1 = *reinterpret_cast<const float2*>(
            w_op + (128 + d) * 64 + 2 * j);
        smu[VU + d * 36 + j] = packbf(v1.x, v1.y);
    }
    __syncthreads();
#pragma unroll
    for (int tt = 0; tt < 2; ++tt) {
        const int ti = warp + tt * 8;
        if (ti < 13) {
            unsigned af[16];
#pragma unroll
            for (int ks = 0; ks < 4; ++ks) {
                const int ar = XU + (ti * 16 + g) * 36 + ks * 8 + tg;
                af[ks*4+0] = smu[ar];     af[ks*4+1] = smu[ar + 288];
                af[ks*4+2] = smu[ar + 4]; af[ks*4+3] = smu[ar + 292];
            }
            float acc1[8][4];
#pragma unroll
            for (int nt = 0; nt < 8; ++nt)
#pragma unroll
                for (int i = 0; i < 4; ++i) acc1[nt][i] = 0.f;
#pragma unroll
            for (int ks = 0; ks < 4; ++ks)
#pragma unroll
                for (int nt = 0; nt < 8; ++nt) {
                    const int br = MISC + (nt * 8 + g) * 36 + ks * 8 + tg;
                    mma16816(acc1[nt], &af[ks * 4], smu[br], smu[br + 4]);
                }
            // bias + pack into GEMM2 A fragments
            unsigned a2[16];
#pragma unroll
            for (int t = 0; t < 4; ++t) {
                const float2 b0 = *reinterpret_cast<const float2*>(
                    b_ao + t * 16 + 2 * tg);
                const float2 b1 = *reinterpret_cast<const float2*>(
                    b_ao + t * 16 + 8 + 2 * tg);
                a2[t*4+0] = packbf(acc1[2*t][0] + b0.x,   acc1[2*t][1] + b0.y);
                a2[t*4+1] = packbf(acc1[2*t][2] + b0.x,   acc1[2*t][3] + b0.y);
                a2[t*4+2] = packbf(acc1[2*t+1][0] + b1.x, acc1[2*t+1][1] + b1.y);
                a2[t*4+3] = packbf(acc1[2*t+1][2] + b1.x, acc1[2*t+1][3] + b1.y);
            }
            const int r0 = ti * 16 + g, r1 = r0 + 8;
#pragma unroll 1
            for (int h2 = 0; h2 < 2; ++h2) {
                const int wb = h2 ? VU : KU;
                const int nb = h2 * 128;
                float acc2[16][4];
#pragma unroll
                for (int nt = 0; nt < 16; ++nt) {
                    const int c = nb + nt * 8 + 2 * tg;
                    const float2 bp = *reinterpret_cast<const float2*>(b_op + c);
                    float2 tA = make_float2(0.f, 0.f), tB = make_float2(0.f, 0.f);
                    if (r0 < NT) tA = *reinterpret_cast<const float2*>(
                        turb_s + (size_t)r0 * CM + c);
                    if (r1 < NT) tB = *reinterpret_cast<const float2*>(
                        turb_s + (size_t)r1 * CM + c);
                    acc2[nt][0] = bp.x + tA.x; acc2[nt][1] = bp.y + tA.y;
                    acc2[nt][2] = bp.x + tB.x; acc2[nt][3] = bp.y + tB.y;
                }
#pragma unroll
                for (int ks = 0; ks < 4; ++ks)
#pragma unroll
                    for (int nt = 0; nt < 16; ++nt) {
                        const int br = wb + (nt * 8 + g) * 36 + ks * 8 + tg;
                        mma16816(acc2[nt], &a2[ks * 4], smu[br], smu[br + 4]);
                    }
#pragma unroll
                for (int nt = 0; nt < 16; ++nt) {
                    const int c = nb + nt * 8 + 2 * tg;
                    if (r0 < NT)
                        *reinterpret_cast<float2*>(out_s + (size_t)r0 * CM + c) =
                            make_float2(acc2[nt][0], acc2[nt][1]);
                    if (r1 < NT)
                        *reinterpret_cast<float2*>(out_s + (size_t)r1 * CM + c) =
                            make_float2(acc2[nt][2], acc2[nt][3]);
                }
            }
        }
    }
}

extern "C" void kernel_launch(void* const* d_in, const int* in_sizes, int n_in,
                              void* d_out, int out_size)
{
    const float* turb  = (const float*)d_in[0];
    const float* weath = (const float*)d_in[1];
    const float* w_t   = (const float*)d_in[2];
    const float* b_t   = (const float*)d_in[3];
    const float* w_w   = (const float*)d_in[4];
    const float* b_w   = (const float*)d_in[5];
    const float* g_t   = (const float*)d_in[6];
    const float* be_t  = (const float*)d_in[7];
    const float* g_w   = (const float*)d_in[8];
    const float* be_w  = (const float*)d_in[9];
    const float* w_qkv = (const float*)d_in[10];
    const float* b_qkv = (const float*)d_in[11];
    const float* w_ao  = (const float*)d_in[12];
    const float* b_ao  = (const float*)d_in[13];
    const float* w_op  = (const float*)d_in[14];
    const float* b_op  = (const float*)d_in[15];
    float* out = (float*)d_out;

    const int S = in_sizes[0] / (NT * CM);   // 768
    const size_t smem = (size_t)SMEM_U * sizeof(unsigned);
    cudaFuncSetAttribute(wda_kernel, cudaFuncAttributeMaxDynamicSharedMemorySize,
                         (int)smem);
    wda_kernel<<<S, NTHR, smem>>>(turb, weath, w_t, b_t, w_w, b_w,
                                  g_t, be_t, g_w, be_w, w_qkv, b_qkv,
                                  w_ao, b_ao, w_op, b_op, out);
}

// round 11
// speedup vs baseline: 3.3496x; 2.1110x over previous
#include <cuda_runtime.h>

// Round 11: full tensor-core pipeline. mma.sync bf16 for stages 1/3/5 AND the
// attention stages 2/4 (logits + PV, P kept in registers). 256 thr, 2 CTAs/SM.

constexpr int NTHR = 256;
constexpr int NT = 200, NW = 100, CM = 256;

// u32 offsets (all matrices [208][36] bf16-pair layout)
constexpr int XU   = 0;              // x/q/o ; S1 A-staging
constexpr int KU   = 7488;           // h_w/K ; S5: w_op half0
constexpr int VU   = 14976;          // h_t/V ; S5: w_op half1
constexpr int MISC = 22464;          // [128][36] weight staging
constexpr int SMEM_U = 27072;        // 108288 bytes

typedef unsigned u32t;

__device__ __forceinline__ unsigned packbf(float lo, float hi) {
    unsigned r;
    asm("cvt.rn.bf16x2.f32 %0, %1, %2;" : "=r"(r) : "f"(hi), "f"(lo));
    return r;
}
__device__ __forceinline__ void mma16816(float* d, const unsigned* a,
                                         unsigned b0, unsigned b1) {
    asm volatile(
        "mma.sync.aligned.m16n8k16.row.col.f32.bf16.bf16.f32 "
        "{%0,%1,%2,%3}, {%4,%5,%6,%7}, {%8,%9}, {%0,%1,%2,%3};"
        : "+f"(d[0]), "+f"(d[1]), "+f"(d[2]), "+f"(d[3])
        : "r"(a[0]), "r"(a[1]), "r"(a[2]), "r"(a[3]), "r"(b0), "r"(b1));
}
__device__ __forceinline__ void ldmT(unsigned& r0, unsigned& r1,
                                     unsigned& r2, unsigned& r3, unsigned addr) {
    asm volatile(
        "ldmatrix.sync.aligned.m8n8.x4.trans.shared.b16 {%0,%1,%2,%3}, [%4];"
        : "=r"(r0), "=r"(r1), "=r"(r2), "=r"(r3) : "r"(addr));
}
__device__ __forceinline__ float red2max(float v) {
    v = fmaxf(v, __shfl_xor_sync(0xffffffffu, v, 1));
    v = fmaxf(v, __shfl_xor_sync(0xffffffffu, v, 2));
    return v;
}
__device__ __forceinline__ float red2sum(float v) {
    v += __shfl_xor_sync(0xffffffffu, v, 1);
    v += __shfl_xor_sync(0xffffffffu, v, 2);
    return v;
}

__global__ __launch_bounds__(NTHR, 2) void wda_kernel(
    const float* __restrict__ turb, const float* __restrict__ weath,
    const float* __restrict__ w_t,  const float* __restrict__ b_t,
    const float* __restrict__ w_w,  const float* __restrict__ b_w,
    const float* __restrict__ g_t,  const float* __restrict__ be_t,
    const float* __restrict__ g_w,  const float* __restrict__ be_w,
    const float* __restrict__ w_qkv,const float* __restrict__ b_qkv,
    const float* __restrict__ w_ao, const float* __restrict__ b_ao,
    const float* __restrict__ w_op, const float* __restrict__ b_op,
    float* __restrict__ out)
{
    extern __shared__ u32t smu[];
    const int tid  = threadIdx.x;
    const int warp = tid >> 5, lane = tid & 31;
    const int g    = lane >> 2, tg = lane & 3;       // mma fragment coords
    const int lrow = lane & 15, lcol = (lane >> 4) * 4;  // ldmatrix coords
    unsigned sb;
    asm("{ .reg .u64 t; cvta.to.shared.u64 t, %1; cvt.u32.u64 %0, t; }"
        : "=r"(sb) : "l"(smu));
    const size_t s = blockIdx.x;
    const float* turb_s  = turb  + s * (size_t)(NT * CM);
    const float* weath_s = weath + s * (size_t)(NW * CM);
    float*       out_s   = out   + s * (size_t)(NT * CM);

    // zero pads: V rows 200..207 (stage-4 PV), h_w rows 100..111 (stage-2 PV)
    for (int i = tid; i < 8 * 36; i += NTHR)  smu[VU + 200 * 36 + i] = 0u;
    for (int i = tid; i < 12 * 36; i += NTHR) smu[KU + 100 * 36 + i] = 0u;

    // ===== Stage 1 (MMA): h = LN(x @ W^T + b) -> h_t in VU, h_w in KU =====
#pragma unroll 1
    for (int src = 0; src < 2; ++src) {
        const float* inp = src ? weath_s : turb_s;
        const float* Wg  = src ? w_w  : w_t;
        const float* bg  = src ? b_w  : b_t;
        const float* gg  = src ? g_w  : g_t;
        const float* beg = src ? be_w : be_t;
        const int rows   = src ? NW : NT;
        const int nT     = src ? 7 : 13;
        const int rstage = nT * 16;
        const int hb     = src ? KU : VU;
        float acc[2][32];
#pragma unroll
        for (int i = 0; i < 2; ++i)
#pragma unroll
            for (int j = 0; j < 32; ++j) acc[i][j] = 0.f;

#pragma unroll 1
        for (int kc = 0; kc < 4; ++kc) {
            __syncthreads();
            for (int idx = tid; idx < rstage * 32; idx += NTHR) {
                const int r = idx >> 5, j = idx & 31;
                const int rr = min(r, rows - 1);
                const float2 v = *reinterpret_cast<const float2*>(
                    inp + (size_t)rr * CM + kc * 64 + 2 * j);
                smu[XU + r * 36 + j] = packbf(v.x, v.y);
            }
            for (int idx = tid; idx < 64 * 32; idx += NTHR) {
                const int d = idx >> 5, j = idx & 31;
                const float2 v = *reinterpret_cast<const float2*>(
                    Wg + d * 256 + kc * 64 + 2 * j);
                smu[MISC + d * 36 + j] = packbf(v.x, v.y);
            }
            __syncthreads();
#pragma unroll
            for (int tt = 0; tt < 2; ++tt) {
                const int ti = warp + tt * 8;
                if (ti < nT) {
#pragma unroll
                    for (int ks = 0; ks < 4; ++ks) {
                        unsigned af[4];
                        const int ar = XU + (ti * 16 + g) * 36 + ks * 8 + tg;
                        af[0] = smu[ar];     af[1] = smu[ar + 288];
                        af[2] = smu[ar + 4]; af[3] = smu[ar + 292];
#pragma unroll
                        for (int nt = 0; nt < 8; ++nt) {
                            const int br = MISC + (nt * 8 + g) * 36 + ks * 8 + tg;
                            mma16816(&acc[tt][nt * 4], af, smu[br], smu[br + 4]);
                        }
                    }
                }
            }
        }
#pragma unroll
        for (int tt = 0; tt < 2; ++tt) {
            const int ti = warp + tt * 8;
            if (ti < nT) {
                float s0 = 0.f, q0 = 0.f, s1 = 0.f, q1 = 0.f;
#pragma unroll
                for (int nt = 0; nt < 8; ++nt) {
                    const float2 bb = *reinterpret_cast<const float2*>(
                        bg + nt * 8 + 2 * tg);
                    float* a = &acc[tt][nt * 4];
                    a[0] += bb.x; a[1] += bb.y; a[2] += bb.x; a[3] += bb.y;
                    s0 += a[0] + a[1]; q0 += a[0]*a[0] + a[1]*a[1];
                    s1 += a[2] + a[3]; q1 += a[2]*a[2] + a[3]*a[3];
                }
                s0 = red2sum(s0); q0 = red2sum(q0);
                s1 = red2sum(s1); q1 = red2sum(q1);
                const float mu0 = s0 * 0.015625f, mu1 = s1 * 0.015625f;
                const float rs0 = rsqrtf(q0 * 0.015625f - mu0 * mu0 + 1e-5f);
                const float rs1 = rsqrtf(q1 * 0.015625f - mu1 * mu1 + 1e-5f);
                const int r0 = ti * 16 + g, r1 = r0 + 8;
#pragma unroll
                for (int nt = 0; nt < 8; ++nt) {
                    const float2 gm = *reinterpret_cast<const float2*>(
                        gg + nt * 8 + 2 * tg);
                    const float2 be = *reinterpret_cast<const float2*>(
                        beg + nt * 8 + 2 * tg);
                    const float* a = &acc[tt][nt * 4];
                    if (r0 < rows)
                        smu[hb + r0 * 36 + nt * 4 + tg] =
                            packbf((a[0]-mu0)*rs0*gm.x + be.x,
                                   (a[1]-mu0)*rs0*gm.y + be.y);
                    if (r1 < rows)
                        smu[hb + r1 * 36 + nt * 4 + tg] =
                            packbf((a[2]-mu1)*rs1*gm.x + be.x,
                                   (a[3]-mu1)*rs1*gm.y + be.y);
                }
            }
        }
    }
    __syncthreads();

    // ===== Stage 2 (MMA attention): x = softmax(h_t h_w^T / 8) h_w ========
#pragma unroll 1
    for (int tt = 0; tt < 2; ++tt) {
        const int ti = warp + tt * 8;
        if (ti < 13) {
            const int rbase = ti * 16;
            float d[13][4];
#pragma unroll
            for (int nt = 0; nt < 13; ++nt)
#pragma unroll
                for (int i = 0; i < 4; ++i) d[nt][i] = 0.f;
            // logits: A = h_t rows (VU), B = h_w rows (KU)
#pragma unroll
            for (int ks = 0; ks < 4; ++ks) {
                unsigned qa[4];
                const int ar = VU + (rbase + g) * 36 + ks * 8 + tg;
                qa[0] = smu[ar];     qa[1] = smu[ar + 288];
                qa[2] = smu[ar + 4]; qa[3] = smu[ar + 292];
#pragma unroll
                for (int nt = 0; nt < 13; ++nt) {
                    const int br = KU + (nt * 8 + g) * 36 + ks * 8 + tg;
                    mma16816(d[nt], qa, smu[br], smu[br + 4]);
                }
            }
            // mask cols >= 100, row max
            float m0 = -1e30f, m1 = -1e30f;
#pragma unroll
            for (int nt = 0; nt < 13; ++nt) {
                const int c0 = nt * 8 + 2 * tg;
                if (c0 >= NW)     { d[nt][0] = -1e30f; d[nt][2] = -1e30f; }
                if (c0 + 1 >= NW) { d[nt][1] = -1e30f; d[nt][3] = -1e30f; }
                m0 = fmaxf(m0, fmaxf(d[nt][0], d[nt][1]));
                m1 = fmaxf(m1, fmaxf(d[nt][2], d[nt][3]));
            }
            m0 = red2max(m0); m1 = red2max(m1);
            float s0 = 0.f, s1 = 0.f;
#pragma unroll
            for (int nt = 0; nt < 13; ++nt) {
                d[nt][0] = __expf((d[nt][0] - m0) * 0.125f);
                d[nt][1] = __expf((d[nt][1] - m0) * 0.125f);
                d[nt][2] = __expf((d[nt][2] - m1) * 0.125f);
                d[nt][3] = __expf((d[nt][3] - m1) * 0.125f);
                s0 += d[nt][0] + d[nt][1];
                s1 += d[nt][2] + d[nt][3];
            }
            s0 = red2sum(s0); s1 = red2sum(s1);
            // PV: P fragments from d, B = h_w via ldmatrix.trans
            float o[8][4];
#pragma unroll
            for (int nt = 0; nt < 8; ++nt)
#pragma unroll
                for (int i = 0; i < 4; ++i) o[nt][i] = 0.f;
#pragma unroll
            for (int kt = 0; kt < 7; ++kt) {
                const float zz[4] = {0.f, 0.f, 0.f, 0.f};
                const float* dA = d[2 * kt];
                const float* dB = (2 * kt + 1 < 13) ? d[2 * kt + 1] : zz;
                unsigned a[4];
                a[0] = packbf(dA[0], dA[1]); a[1] = packbf(dA[2], dA[3]);
                a[2] = packbf(dB[0], dB[1]); a[3] = packbf(dB[2], dB[3]);
#pragma unroll
                for (int np = 0; np < 4; ++np) {
                    unsigned b0, b1, b2, b3;
                    const unsigned ad = sb + 4u *
                        (KU + (kt * 16 + lrow) * 36 + np * 8 + lcol);
                    ldmT(b0, b1, b2, b3, ad);
                    mma16816(o[2 * np],     a, b0, b1);
                    mma16816(o[2 * np + 1], a, b2, b3);
                }
            }
            const float i0 = 1.f / s0, i1 = 1.f / s1;
            const int r0 = rbase + g, r1 = r0 + 8;
#pragma unroll
            for (int nt = 0; nt < 8; ++nt) {
                if (r0 < NT)
                    smu[XU + r0 * 36 + nt * 4 + tg] =
                        packbf(o[nt][0] * i0, o[nt][1] * i0);
                if (r1 < NT)
                    smu[XU + r1 * 36 + nt * 4 + tg] =
                        packbf(o[nt][2] * i1, o[nt][3] * i1);
            }
        }
    }
    __syncthreads();

    // ===== Stage 3 (MMA): qkv = x @ Wqkv^T + b; half0: k,v; half1: q ======
#pragma unroll 1
    for (int h = 0; h < 2; ++h) {
        __syncthreads();
        const int nbase = h ? 0 : 64;
        const int ncols = h ? 64 : 128;
        for (int idx = tid; idx < ncols * 32; idx += NTHR) {
            const int d = idx >> 5, j = idx & 31;
            const float2 v = *reinterpret_cast<const float2*>(
                w_qkv + (nbase + d) * 64 + 2 * j);
            smu[MISC + d * 36 + j] = packbf(v.x, v.y);
        }
        __syncthreads();
#pragma unroll
        for (int tt = 0; tt < 2; ++tt) {
            const int ti = warp + tt * 8;
            if (ti < 13) {
                unsigned af[16];
#pragma unroll
                for (int ks = 0; ks < 4; ++ks) {
                    const int ar = XU + (ti * 16 + g) * 36 + ks * 8 + tg;
                    af[ks*4+0] = smu[ar];     af[ks*4+1] = smu[ar + 288];
                    af[ks*4+2] = smu[ar + 4]; af[ks*4+3] = smu[ar + 292];
                }
                const int r0 = ti * 16 + g, r1 = r0 + 8;
                if (h == 0) {
                    float acc[16][4];
#pragma unroll
                    for (int nt = 0; nt < 16; ++nt)
#pragma unroll
                        for (int i = 0; i < 4; ++i) acc[nt][i] = 0.f;
#pragma unroll
                    for (int ks = 0; ks < 4; ++ks)
#pragma unroll
                        for (int nt = 0; nt < 16; ++nt) {
                            const int br = MISC + (nt * 8 + g) * 36 + ks * 8 + tg;
                            mma16816(acc[nt], &af[ks * 4], smu[br], smu[br + 4]);
                        }
#pragma unroll
                    for (int nt = 0; nt < 16; ++nt) {
                        const float2 bb = *reinterpret_cast<const float2*>(
                            b_qkv + 64 + nt * 8 + 2 * tg);
                        const int base = (nt < 8) ? KU : VU;
                        const int cc = (nt & 7) * 4 + tg;
                        if (r0 < NT)
                            smu[base + r0 * 36 + cc] =
                                packbf(acc[nt][0] + bb.x, acc[nt][1] + bb.y);
                        if (r1 < NT)
                            smu[base + r1 * 36 + cc] =
                                packbf(acc[nt][2] + bb.x, acc[nt][3] + bb.y);
                    }
                } else {
                    float acc[8][4];
#pragma unroll
                    for (int nt = 0; nt < 8; ++nt)
#pragma unroll
                        for (int i = 0; i < 4; ++i) acc[nt][i] = 0.f;
#pragma unroll
                    for (int ks = 0; ks < 4; ++ks)
#pragma unroll
                        for (int nt = 0; nt < 8; ++nt) {
                            const int br = MISC + (nt * 8 + g) * 36 + ks * 8 + tg;
                            mma16816(acc[nt], &af[ks * 4], smu[br], smu[br + 4]);
                        }
#pragma unroll
                    for (int nt = 0; nt < 8; ++nt) {
                        const float2 bb = *reinterpret_cast<const float2*>(
                            b_qkv + nt * 8 + 2 * tg);
                        const int cc = nt * 4 + tg;
                        if (r0 < NT)
                            smu[XU + r0 * 36 + cc] =
                                packbf(acc[nt][0] + bb.x, acc[nt][1] + bb.y);
                        if (r1 < NT)
                            smu[XU + r1 * 36 + cc] =
                                packbf(acc[nt][2] + bb.x, acc[nt][3] + bb.y);
                    }
                }
            }
        }
    }
    __syncthreads();

    // ===== Stage 4 (MMA attention): o = softmax(q k^T / 4) v, per head ====
#pragma unroll 1
    for (int tt = 0; tt < 2; ++tt) {
        const int ti = warp + tt * 8;
        if (ti < 13) {
            const int rbase = ti * 16;
#pragma unroll 1
            for (int h = 0; h < 4; ++h) {
                unsigned qa[4];
                const int ar = XU + (rbase + g) * 36 + h * 8 + tg;
                qa[0] = smu[ar];     qa[1] = smu[ar + 288];
                qa[2] = smu[ar + 4]; qa[3] = smu[ar + 292];
                // pass 1: row max (25 n-tiles = cols 0..199, no mask needed)
                float m0 = -1e30f, m1 = -1e30f;
#pragma unroll
                for (int nt = 0; nt < 25; ++nt) {
                    float dd[4] = {0.f, 0.f, 0.f, 0.f};
                    const int br = KU + (nt * 8 + g) * 36 + h * 8 + tg;
                    mma16816(dd, qa, smu[br], smu[br + 4]);
                    m0 = fmaxf(m0, fmaxf(dd[0], dd[1]));
                    m1 = fmaxf(m1, fmaxf(dd[2], dd[3]));
                }
                m0 = red2max(m0); m1 = red2max(m1);
                // pass 2: recompute, exp, PV
                float s0 = 0.f, s1 = 0.f;
                float o0[4] = {0.f,0.f,0.f,0.f}, o1[4] = {0.f,0.f,0.f,0.f};
#pragma unroll
                for (int kt = 0; kt < 13; ++kt) {
                    float dA[4] = {0.f,0.f,0.f,0.f}, dB[4] = {0.f,0.f,0.f,0.f};
                    {
                        const int br = KU + (kt * 16 + g) * 36 + h * 8 + tg;
                        mma16816(dA, qa, smu[br], smu[br + 4]);
                    }
                    float eB0 = 0.f, eB1 = 0.f, eB2 = 0.f, eB3 = 0.f;
                    if (kt < 12) {
                        const int br = KU + (kt * 16 + 8 + g) * 36 + h * 8 + tg;
                        mma16816(dB, qa, smu[br], smu[br + 4]);
                        eB0 = __expf((dB[0] - m0) * 0.25f);
                        eB1 = __expf((dB[1] - m0) * 0.25f);
                        eB2 = __expf((dB[2] - m1) * 0.25f);
                        eB3 = __expf((dB[3] - m1) * 0.25f);
                    }
                    const float eA0 = __expf((dA[0] - m0) * 0.25f);
                    const float eA1 = __expf((dA[1] - m0) * 0.25f);
                    const float eA2 = __expf((dA[2] - m1) * 0.25f);
                    const float eA3 = __expf((dA[3] - m1) * 0.25f);
                    s0 += eA0 + eA1 + eB0 + eB1;
                    s1 += eA2 + eA3 + eB2 + eB3;
                    unsigned a[4];
                    a[0] = packbf(eA0, eA1); a[1] = packbf(eA2, eA3);
                    a[2] = packbf(eB0, eB1); a[3] = packbf(eB2, eB3);
                    unsigned b0, b1, b2, b3;
                    const unsigned ad = sb + 4u *
                        (VU + (kt * 16 + lrow) * 36 + h * 8 + lcol);
                    ldmT(b0, b1, b2, b3, ad);
                    mma16816(o0, a, b0, b1);
                    mma16816(o1, a, b2, b3);
                }
                s0 = red2sum(s0); s1 = red2sum(s1);
                const float i0 = 1.f / s0, i1 = 1.f / s1;
                const int r0 = rbase + g, r1 = r0 + 8;
                if (r0 < NT) {
                    smu[XU + r0 * 36 + h * 8 + tg] =
                        packbf(o0[0] * i0, o0[1] * i0);
                    smu[XU + r0 * 36 + h * 8 + 4 + tg] =
                        packbf(o1[0] * i0, o1[1] * i0);
                }
                if (r1 < NT) {
                    smu[XU + r1 * 36 + h * 8 + tg] =
                        packbf(o0[2] * i1, o0[3] * i1);
                    smu[XU + r1 * 36 + h * 8 + 4 + tg] =
                        packbf(o1[2] * i1, o1[3] * i1);
                }
            }
        }
    }
    __syncthreads();

    // ===== Stage 5 (MMA): A1 = o@aoT + b_ao; out = turb + A1@opT + b_op ===
    for (int idx = tid; idx < 64 * 32; idx += NTHR) {
        const int d = idx >> 5, j = idx & 31;
        const float2 v = *reinterpret_cast<const float2*>(w_ao + d * 64 + 2 * j);
        smu[MISC + d * 36 + j] = packbf(v.x, v.y);
    }
    for (int idx = tid; idx < 128 * 32; idx += NTHR) {
        const int d = idx >> 5, j = idx & 31;
        const float2 v0 = *reinterpret_cast<const float2*>(w_op + d * 64 + 2 * j);
        smu[KU + d * 36 + j] = packbf(v0.x, v0.y);
        const float2 v1 = *reinterpret_cast<const float2*>(
            w_op + (128 + d) * 64 + 2 * j);
        smu[VU + d * 36 + j] = packbf(v1.x, v1.y);
    }
    __syncthreads();
#pragma unroll
    for (int tt = 0; tt < 2; ++tt) {
        const int ti = warp + tt * 8;
        if (ti < 13) {
            unsigned af[16];
#pragma unroll
            for (int ks = 0; ks < 4; ++ks) {
                const int ar = XU + (ti * 16 + g) * 36 + ks * 8 + tg;
                af[ks*4+0] = smu[ar];     af[ks*4+1] = smu[ar + 288];
                af[ks*4+2] = smu[ar + 4]; af[ks*4+3] = smu[ar + 292];
            }
            float acc1[8][4];
#pragma unroll
            for (int nt = 0; nt < 8; ++nt)
#pragma unroll
                for (int i = 0; i < 4; ++i) acc1[nt][i] = 0.f;
#pragma unroll
            for (int ks = 0; ks < 4; ++ks)
#pragma unroll
                for (int nt = 0; nt < 8; ++nt) {
                    const int br = MISC + (nt * 8 + g) * 36 + ks * 8 + tg;
                    mma16816(acc1[nt], &af[ks * 4], smu[br], smu[br + 4]);
                }
            unsigned a2[16];
#pragma unroll
            for (int t = 0; t < 4; ++t) {
                const float2 b0 = *reinterpret_cast<const float2*>(
                    b_ao + t * 16 + 2 * tg);
                const float2 b1 = *reinterpret_cast<const float2*>(
                    b_ao + t * 16 + 8 + 2 * tg);
                a2[t*4+0] = packbf(acc1[2*t][0] + b0.x,   acc1[2*t][1] + b0.y);
                a2[t*4+1] = packbf(acc1[2*t][2] + b0.x,   acc1[2*t][3] + b0.y);
                a2[t*4+2] = packbf(acc1[2*t+1][0] + b1.x, acc1[2*t+1][1] + b1.y);
                a2[t*4+3] = packbf(acc1[2*t+1][2] + b1.x, acc1[2*t+1][3] + b1.y);
            }
            const int r0 = ti * 16 + g, r1 = r0 + 8;
#pragma unroll 1
            for (int h2 = 0; h2 < 2; ++h2) {
                const int wb = h2 ? VU : KU;
                const int nb = h2 * 128;
                float acc2[16][4];
#pragma unroll
                for (int nt = 0; nt < 16; ++nt) {
                    const int c = nb + nt * 8 + 2 * tg;
                    const float2 bp = *reinterpret_cast<const float2*>(b_op + c);
                    float2 tA = make_float2(0.f, 0.f), tB = make_float2(0.f, 0.f);
                    if (r0 < NT) tA = *reinterpret_cast<const float2*>(
                        turb_s + (size_t)r0 * CM + c);
                    if (r1 < NT) tB = *reinterpret_cast<const float2*>(
                        turb_s + (size_t)r1 * CM + c);
                    acc2[nt][0] = bp.x + tA.x; acc2[nt][1] = bp.y + tA.y;
                    acc2[nt][2] = bp.x + tB.x; acc2[nt][3] = bp.y + tB.y;
                }
#pragma unroll
                for (int ks = 0; ks < 4; ++ks)
#pragma unroll
                    for (int nt = 0; nt < 16; ++nt) {
                        const int br = wb + (nt * 8 + g) * 36 + ks * 8 + tg;
                        mma16816(acc2[nt], &a2[ks * 4], smu[br], smu[br + 4]);
                    }
#pragma unroll
                for (int nt = 0; nt < 16; ++nt) {
                    const int c = nb + nt * 8 + 2 * tg;
                    if (r0 < NT)
                        *reinterpret_cast<float2*>(out_s + (size_t)r0 * CM + c) =
                            make_float2(acc2[nt][0], acc2[nt][1]);
                    if (r1 < NT)
                        *reinterpret_cast<float2*>(out_s + (size_t)r1 * CM + c) =
                            make_float2(acc2[nt][2], acc2[nt][3]);
                }
            }
        }
    }
}

extern "C" void kernel_launch(void* const* d_in, const int* in_sizes, int n_in,
                              void* d_out, int out_size)
{
    const float* turb  = (const float*)d_in[0];
    const float* weath = (const float*)d_in[1];
    const float* w_t   = (const float*)d_in[2];
    const float* b_t   = (const float*)d_in[3];
    const float* w_w   = (const float*)d_in[4];
    const float* b_w   = (const float*)d_in[5];
    const float* g_t   = (const float*)d_in[6];
    const float* be_t  = (const float*)d_in[7];
    const float* g_w   = (const float*)d_in[8];
    const float* be_w  = (const float*)d_in[9];
    const float* w_qkv = (const float*)d_in[10];
    const float* b_qkv = (const float*)d_in[11];
    const float* w_ao  = (const float*)d_in[12];
    const float* b_ao  = (const float*)d_in[13];
    const float* w_op  = (const float*)d_in[14];
    const float* b_op  = (const float*)d_in[15];
    float* out = (float*)d_out;

    const int S = in_sizes[0] / (NT * CM);   // 768
    const size_t smem = (size_t)SMEM_U * sizeof(unsigned);
    cudaFuncSetAttribute(wda_kernel, cudaFuncAttributeMaxDynamicSharedMemorySize,
                         (int)smem);
    wda_kernel<<<S, NTHR, smem>>>(turb, weath, w_t, b_t, w_w, b_w,
                                  g_t, be_t, g_w, be_w, w_qkv, b_qkv,
                                  w_ao, b_ao, w_op, b_op, out);
}

// round 12
// speedup vs baseline: 3.5739x; 1.0670x over previous
#include <cuda_runtime.h>

// Round 12: stage-4 single-pass softmax (no max prescan) + flattened (ti,h)
// work distribution; stage-2 max dropped. Rest = Round 11.

constexpr int NTHR = 256;
constexpr int NT = 200, NW = 100, CM = 256;

// u32 offsets (all matrices [208][36] bf16-pair layout)
constexpr int XU   = 0;              // x/q/o ; S1 A-staging
constexpr int KU   = 7488;           // h_w/K ; S5: w_op half0
constexpr int VU   = 14976;          // h_t/V ; S5: w_op half1
constexpr int MISC = 22464;          // [128][36] weight staging
constexpr int SMEM_U = 27072;        // 108288 bytes

typedef unsigned u32t;

__device__ __forceinline__ unsigned packbf(float lo, float hi) {
    unsigned r;
    asm("cvt.rn.bf16x2.f32 %0, %1, %2;" : "=r"(r) : "f"(hi), "f"(lo));
    return r;
}
__device__ __forceinline__ void mma16816(float* d, const unsigned* a,
                                         unsigned b0, unsigned b1) {
    asm volatile(
        "mma.sync.aligned.m16n8k16.row.col.f32.bf16.bf16.f32 "
        "{%0,%1,%2,%3}, {%4,%5,%6,%7}, {%8,%9}, {%0,%1,%2,%3};"
        : "+f"(d[0]), "+f"(d[1]), "+f"(d[2]), "+f"(d[3])
        : "r"(a[0]), "r"(a[1]), "r"(a[2]), "r"(a[3]), "r"(b0), "r"(b1));
}
__device__ __forceinline__ void ldmT(unsigned& r0, unsigned& r1,
                                     unsigned& r2, unsigned& r3, unsigned addr) {
    asm volatile(
        "ldmatrix.sync.aligned.m8n8.x4.trans.shared.b16 {%0,%1,%2,%3}, [%4];"
        : "=r"(r0), "=r"(r1), "=r"(r2), "=r"(r3) : "r"(addr));
}
__device__ __forceinline__ float red2sum(float v) {
    v += __shfl_xor_sync(0xffffffffu, v, 1);
    v += __shfl_xor_sync(0xffffffffu, v, 2);
    return v;
}

__global__ __launch_bounds__(NTHR, 2) void wda_kernel(
    const float* __restrict__ turb, const float* __restrict__ weath,
    const float* __restrict__ w_t,  const float* __restrict__ b_t,
    const float* __restrict__ w_w,  const float* __restrict__ b_w,
    const float* __restrict__ g_t,  const float* __restrict__ be_t,
    const float* __restrict__ g_w,  const float* __restrict__ be_w,
    const float* __restrict__ w_qkv,const float* __restrict__ b_qkv,
    const float* __restrict__ w_ao, const float* __restrict__ b_ao,
    const float* __restrict__ w_op, const float* __restrict__ b_op,
    float* __restrict__ out)
{
    extern __shared__ u32t smu[];
    const int tid  = threadIdx.x;
    const int warp = tid >> 5, lane = tid & 31;
    const int g    = lane >> 2, tg = lane & 3;       // mma fragment coords
    const int lrow = lane & 15, lcol = (lane >> 4) * 4;  // ldmatrix coords
    unsigned sb;
    asm("{ .reg .u64 t; cvta.to.shared.u64 t, %1; cvt.u32.u64 %0, t; }"
        : "=r"(sb) : "l"(smu));
    const size_t s = blockIdx.x;
    const float* turb_s  = turb  + s * (size_t)(NT * CM);
    const float* weath_s = weath + s * (size_t)(NW * CM);
    float*       out_s   = out   + s * (size_t)(NT * CM);

    // zero pads: V rows 200..207 (stage-4 PV), h_w rows 100..111 (stage-2 PV)
    for (int i = tid; i < 8 * 36; i += NTHR)  smu[VU + 200 * 36 + i] = 0u;
    for (int i = tid; i < 12 * 36; i += NTHR) smu[KU + 100 * 36 + i] = 0u;

    // ===== Stage 1 (MMA): h = LN(x @ W^T + b) -> h_t in VU, h_w in KU =====
#pragma unroll 1
    for (int src = 0; src < 2; ++src) {
        const float* inp = src ? weath_s : turb_s;
        const float* Wg  = src ? w_w  : w_t;
        const float* bg  = src ? b_w  : b_t;
        const float* gg  = src ? g_w  : g_t;
        const float* beg = src ? be_w : be_t;
        const int rows   = src ? NW : NT;
        const int nT     = src ? 7 : 13;
        const int rstage = nT * 16;
        const int hb     = src ? KU : VU;
        float acc[2][32];
#pragma unroll
        for (int i = 0; i < 2; ++i)
#pragma unroll
            for (int j = 0; j < 32; ++j) acc[i][j] = 0.f;

#pragma unroll 1
        for (int kc = 0; kc < 4; ++kc) {
            __syncthreads();
            for (int idx = tid; idx < rstage * 32; idx += NTHR) {
                const int r = idx >> 5, j = idx & 31;
                const int rr = min(r, rows - 1);
                const float2 v = *reinterpret_cast<const float2*>(
                    inp + (size_t)rr * CM + kc * 64 + 2 * j);
                smu[XU + r * 36 + j] = packbf(v.x, v.y);
            }
            for (int idx = tid; idx < 64 * 32; idx += NTHR) {
                const int d = idx >> 5, j = idx & 31;
                const float2 v = *reinterpret_cast<const float2*>(
                    Wg + d * 256 + kc * 64 + 2 * j);
                smu[MISC + d * 36 + j] = packbf(v.x, v.y);
            }
            __syncthreads();
#pragma unroll
            for (int tt = 0; tt < 2; ++tt) {
                const int ti = warp + tt * 8;
                if (ti < nT) {
#pragma unroll
                    for (int ks = 0; ks < 4; ++ks) {
                        unsigned af[4];
                        const int ar = XU + (ti * 16 + g) * 36 + ks * 8 + tg;
                        af[0] = smu[ar];     af[1] = smu[ar + 288];
                        af[2] = smu[ar + 4]; af[3] = smu[ar + 292];
#pragma unroll
                        for (int nt = 0; nt < 8; ++nt) {
                            const int br = MISC + (nt * 8 + g) * 36 + ks * 8 + tg;
                            mma16816(&acc[tt][nt * 4], af, smu[br], smu[br + 4]);
                        }
                    }
                }
            }
        }
#pragma unroll
        for (int tt = 0; tt < 2; ++tt) {
            const int ti = warp + tt * 8;
            if (ti < nT) {
                float s0 = 0.f, q0 = 0.f, s1 = 0.f, q1 = 0.f;
#pragma unroll
                for (int nt = 0; nt < 8; ++nt) {
                    const float2 bb = *reinterpret_cast<const float2*>(
                        bg + nt * 8 + 2 * tg);
                    float* a = &acc[tt][nt * 4];
                    a[0] += bb.x; a[1] += bb.y; a[2] += bb.x; a[3] += bb.y;
                    s0 += a[0] + a[1]; q0 += a[0]*a[0] + a[1]*a[1];
                    s1 += a[2] + a[3]; q1 += a[2]*a[2] + a[3]*a[3];
                }
                s0 = red2sum(s0); q0 = red2sum(q0);
                s1 = red2sum(s1); q1 = red2sum(q1);
                const float mu0 = s0 * 0.015625f, mu1 = s1 * 0.015625f;
                const float rs0 = rsqrtf(q0 * 0.015625f - mu0 * mu0 + 1e-5f);
                const float rs1 = rsqrtf(q1 * 0.015625f - mu1 * mu1 + 1e-5f);
                const int r0 = ti * 16 + g, r1 = r0 + 8;
#pragma unroll
                for (int nt = 0; nt < 8; ++nt) {
                    const float2 gm = *reinterpret_cast<const float2*>(
                        gg + nt * 8 + 2 * tg);
                    const float2 be = *reinterpret_cast<const float2*>(
                        beg + nt * 8 + 2 * tg);
                    const float* a = &acc[tt][nt * 4];
                    if (r0 < rows)
                        smu[hb + r0 * 36 + nt * 4 + tg] =
                            packbf((a[0]-mu0)*rs0*gm.x + be.x,
                                   (a[1]-mu0)*rs0*gm.y + be.y);
                    if (r1 < rows)
                        smu[hb + r1 * 36 + nt * 4 + tg] =
                            packbf((a[2]-mu1)*rs1*gm.x + be.x,
                                   (a[3]-mu1)*rs1*gm.y + be.y);
                }
            }
        }
    }
    __syncthreads();

    // ===== Stage 2 (MMA attention): x = softmax(h_t h_w^T / 8) h_w ========
    // logits bounded (|l|<~8): exp without max subtraction is safe.
#pragma unroll 1
    for (int tt = 0; tt < 2; ++tt) {
        const int ti = warp + tt * 8;
        if (ti < 13) {
            const int rbase = ti * 16;
            float d[13][4];
#pragma unroll
            for (int nt = 0; nt < 13; ++nt)
#pragma unroll
                for (int i = 0; i < 4; ++i) d[nt][i] = 0.f;
#pragma unroll
            for (int ks = 0; ks < 4; ++ks) {
                unsigned qa[4];
                const int ar = VU + (rbase + g) * 36 + ks * 8 + tg;
                qa[0] = smu[ar];     qa[1] = smu[ar + 288];
                qa[2] = smu[ar + 4]; qa[3] = smu[ar + 292];
#pragma unroll
                for (int nt = 0; nt < 13; ++nt) {
                    const int br = KU + (nt * 8 + g) * 36 + ks * 8 + tg;
                    mma16816(d[nt], qa, smu[br], smu[br + 4]);
                }
            }
            float s0 = 0.f, s1 = 0.f;
#pragma unroll
            for (int nt = 0; nt < 13; ++nt) {
                const int c0 = nt * 8 + 2 * tg;
                const bool ok0 = c0 < NW, ok1 = c0 + 1 < NW;
                d[nt][0] = ok0 ? __expf(d[nt][0] * 0.125f) : 0.f;
                d[nt][1] = ok1 ? __expf(d[nt][1] * 0.125f) : 0.f;
                d[nt][2] = ok0 ? __expf(d[nt][2] * 0.125f) : 0.f;
                d[nt][3] = ok1 ? __expf(d[nt][3] * 0.125f) : 0.f;
                s0 += d[nt][0] + d[nt][1];
                s1 += d[nt][2] + d[nt][3];
            }
            s0 = red2sum(s0); s1 = red2sum(s1);
            float o[8][4];
#pragma unroll
            for (int nt = 0; nt < 8; ++nt)
#pragma unroll
                for (int i = 0; i < 4; ++i) o[nt][i] = 0.f;
#pragma unroll
            for (int kt = 0; kt < 7; ++kt) {
                const float zz[4] = {0.f, 0.f, 0.f, 0.f};
                const float* dA = d[2 * kt];
                const float* dB = (2 * kt + 1 < 13) ? d[2 * kt + 1] : zz;
                unsigned a[4];
                a[0] = packbf(dA[0], dA[1]); a[1] = packbf(dA[2], dA[3]);
                a[2] = packbf(dB[0], dB[1]); a[3] = packbf(dB[2], dB[3]);
#pragma unroll
                for (int np = 0; np < 4; ++np) {
                    unsigned b0, b1, b2, b3;
                    const unsigned ad = sb + 4u *
                        (KU + (kt * 16 + lrow) * 36 + np * 8 + lcol);
                    ldmT(b0, b1, b2, b3, ad);
                    mma16816(o[2 * np],     a, b0, b1);
                    mma16816(o[2 * np + 1], a, b2, b3);
                }
            }
            const float i0 = 1.f / s0, i1 = 1.f / s1;
            const int r0 = rbase + g, r1 = r0 + 8;
#pragma unroll
            for (int nt = 0; nt < 8; ++nt) {
                if (r0 < NT)
                    smu[XU + r0 * 36 + nt * 4 + tg] =
                        packbf(o[nt][0] * i0, o[nt][1] * i0);
                if (r1 < NT)
                    smu[XU + r1 * 36 + nt * 4 + tg] =
                        packbf(o[nt][2] * i1, o[nt][3] * i1);
            }
        }
    }
    __syncthreads();

    // ===== Stage 3 (MMA): qkv = x @ Wqkv^T + b; half0: k,v; half1: q ======
#pragma unroll 1
    for (int h = 0; h < 2; ++h) {
        __syncthreads();
        const int nbase = h ? 0 : 64;
        const int ncols = h ? 64 : 128;
        for (int idx = tid; idx < ncols * 32; idx += NTHR) {
            const int d = idx >> 5, j = idx & 31;
            const float2 v = *reinterpret_cast<const float2*>(
                w_qkv + (nbase + d) * 64 + 2 * j);
            smu[MISC + d * 36 + j] = packbf(v.x, v.y);
        }
        __syncthreads();
#pragma unroll
        for (int tt = 0; tt < 2; ++tt) {
            const int ti = warp + tt * 8;
            if (ti < 13) {
                unsigned af[16];
#pragma unroll
                for (int ks = 0; ks < 4; ++ks) {
                    const int ar = XU + (ti * 16 + g) * 36 + ks * 8 + tg;
                    af[ks*4+0] = smu[ar];     af[ks*4+1] = smu[ar + 288];
                    af[ks*4+2] = smu[ar + 4]; af[ks*4+3] = smu[ar + 292];
                }
                const int r0 = ti * 16 + g, r1 = r0 + 8;
                if (h == 0) {
                    float acc[16][4];
#pragma unroll
                    for (int nt = 0; nt < 16; ++nt)
#pragma unroll
                        for (int i = 0; i < 4; ++i) acc[nt][i] = 0.f;
#pragma unroll
                    for (int ks = 0; ks < 4; ++ks)
#pragma unroll
                        for (int nt = 0; nt < 16; ++nt) {
                            const int br = MISC + (nt * 8 + g) * 36 + ks * 8 + tg;
                            mma16816(acc[nt], &af[ks * 4], smu[br], smu[br + 4]);
                        }
#pragma unroll
                    for (int nt = 0; nt < 16; ++nt) {
                        const float2 bb = *reinterpret_cast<const float2*>(
                            b_qkv + 64 + nt * 8 + 2 * tg);
                        const int base = (nt < 8) ? KU : VU;
                        const int cc = (nt & 7) * 4 + tg;
                        if (r0 < NT)
                            smu[base + r0 * 36 + cc] =
                                packbf(acc[nt][0] + bb.x, acc[nt][1] + bb.y);
                        if (r1 < NT)
                            smu[base + r1 * 36 + cc] =
                                packbf(acc[nt][2] + bb.x, acc[nt][3] + bb.y);
                    }
                } else {
                    float acc[8][4];
#pragma unroll
                    for (int nt = 0; nt < 8; ++nt)
#pragma unroll
                        for (int i = 0; i < 4; ++i) acc[nt][i] = 0.f;
#pragma unroll
                    for (int ks = 0; ks < 4; ++ks)
#pragma unroll
                        for (int nt = 0; nt < 8; ++nt) {
                            const int br = MISC + (nt * 8 + g) * 36 + ks * 8 + tg;
                            mma16816(acc[nt], &af[ks * 4], smu[br], smu[br + 4]);
                        }
#pragma unroll
                    for (int nt = 0; nt < 8; ++nt) {
                        const float2 bb = *reinterpret_cast<const float2*>(
                            b_qkv + nt * 8 + 2 * tg);
                        const int cc = nt * 4 + tg;
                        if (r0 < NT)
                            smu[XU + r0 * 36 + cc] =
                                packbf(acc[nt][0] + bb.x, acc[nt][1] + bb.y);
                        if (r1 < NT)
                            smu[XU + r1 * 36 + cc] =
                                packbf(acc[nt][2] + bb.x, acc[nt][3] + bb.y);
                    }
                }
            }
        }
    }
    __syncthreads();

    // ===== Stage 4 (MMA attention): o = softmax(q k^T / 4) v ==============
    // single-pass (|logit| tiny -> no max needed); 52 (ti,h) units over warps
#pragma unroll 1
    for (int u = warp; u < 52; u += 8) {
        const int ti = u >> 2, h = u & 3;
        const int rbase = ti * 16;
        unsigned qa[4];
        const int ar = XU + (rbase + g) * 36 + h * 8 + tg;
        qa[0] = smu[ar];     qa[1] = smu[ar + 288];
        qa[2] = smu[ar + 4]; qa[3] = smu[ar + 292];
        float s0 = 0.f, s1 = 0.f;
        float o0[4] = {0.f,0.f,0.f,0.f}, o1[4] = {0.f,0.f,0.f,0.f};
#pragma unroll
        for (int kt = 0; kt < 13; ++kt) {
            float dA[4] = {0.f,0.f,0.f,0.f}, dB[4] = {0.f,0.f,0.f,0.f};
            {
                const int br = KU + (kt * 16 + g) * 36 + h * 8 + tg;
                mma16816(dA, qa, smu[br], smu[br + 4]);
            }
            float eB0 = 0.f, eB1 = 0.f, eB2 = 0.f, eB3 = 0.f;
            if (kt < 12) {
                const int br = KU + (kt * 16 + 8 + g) * 36 + h * 8 + tg;
                mma16816(dB, qa, smu[br], smu[br + 4]);
                eB0 = __expf(dB[0] * 0.25f);
                eB1 = __expf(dB[1] * 0.25f);
                eB2 = __expf(dB[2] * 0.25f);
                eB3 = __expf(dB[3] * 0.25f);
            }
            const float eA0 = __expf(dA[0] * 0.25f);
            const float eA1 = __expf(dA[1] * 0.25f);
            const float eA2 = __expf(dA[2] * 0.25f);
            const float eA3 = __expf(dA[3] * 0.25f);
            s0 += eA0 + eA1 + eB0 + eB1;
            s1 += eA2 + eA3 + eB2 + eB3;
            unsigned a[4];
            a[0] = packbf(eA0, eA1); a[1] = packbf(eA2, eA3);
            a[2] = packbf(eB0, eB1); a[3] = packbf(eB2, eB3);
            unsigned b0, b1, b2, b3;
            const unsigned ad = sb + 4u *
                (VU + (kt * 16 + lrow) * 36 + h * 8 + lcol);
            ldmT(b0, b1, b2, b3, ad);
            mma16816(o0, a, b0, b1);
            mma16816(o1, a, b2, b3);
        }
        s0 = red2sum(s0); s1 = red2sum(s1);
        const float i0 = 1.f / s0, i1 = 1.f / s1;
        const int r0 = rbase + g, r1 = r0 + 8;
        if (r0 < NT) {
            smu[XU + r0 * 36 + h * 8 + tg]     = packbf(o0[0] * i0, o0[1] * i0);
            smu[XU + r0 * 36 + h * 8 + 4 + tg] = packbf(o1[0] * i0, o1[1] * i0);
        }
        if (r1 < NT) {
            smu[XU + r1 * 36 + h * 8 + tg]     = packbf(o0[2] * i1, o0[3] * i1);
            smu[XU + r1 * 36 + h * 8 + 4 + tg] = packbf(o1[2] * i1, o1[3] * i1);
        }
    }
    __syncthreads();

    // ===== Stage 5 (MMA): A1 = o@aoT + b_ao; out = turb + A1@opT + b_op ===
    for (int idx = tid; idx < 64 * 32; idx += NTHR) {
        const int d = idx >> 5, j = idx & 31;
        const float2 v = *reinterpret_cast<const float2*>(w_ao + d * 64 + 2 * j);
        smu[MISC + d * 36 + j] = packbf(v.x, v.y);
    }
    for (int idx = tid; idx < 128 * 32; idx += NTHR) {
        const int d = idx >> 5, j = idx & 31;
        const float2 v0 = *reinterpret_cast<const float2*>(w_op + d * 64 + 2 * j);
        smu[KU + d * 36 + j] = packbf(v0.x, v0.y);
        const float2 v1 = *reinterpret_cast<const float2*>(
            w_op + (128 + d) * 64 + 2 * j);
        smu[VU + d * 36 + j] = packbf(v1.x, v1.y);
    }
    __syncthreads();
#pragma unroll
    for (int tt = 0; tt < 2; ++tt) {
        const int ti = warp + tt * 8;
        if (ti < 13) {
            unsigned af[16];
#pragma unroll
            for (int ks = 0; ks < 4; ++ks) {
                const int ar = XU + (ti * 16 + g) * 36 + ks * 8 + tg;
                af[ks*4+0] = smu[ar];     af[ks*4+1] = smu[ar + 288];
                af[ks*4+2] = smu[ar + 4]; af[ks*4+3] = smu[ar + 292];
            }
            float acc1[8][4];
#pragma unroll
            for (int nt = 0; nt < 8; ++nt)
#pragma unroll
                for (int i = 0; i < 4; ++i) acc1[nt][i] = 0.f;
#pragma unroll
            for (int ks = 0; ks < 4; ++ks)
#pragma unroll
                for (int nt = 0; nt < 8; ++nt) {
                    const int br = MISC + (nt * 8 + g) * 36 + ks * 8 + tg;
                    mma16816(acc1[nt], &af[ks * 4], smu[br], smu[br + 4]);
                }
            unsigned a2[16];
#pragma unroll
            for (int t = 0; t < 4; ++t) {
                const float2 b0 = *reinterpret_cast<const float2*>(
                    b_ao + t * 16 + 2 * tg);
                const float2 b1 = *reinterpret_cast<const float2*>(
                    b_ao + t * 16 + 8 + 2 * tg);
                a2[t*4+0] = packbf(acc1[2*t][0] + b0.x,   acc1[2*t][1] + b0.y);
                a2[t*4+1] = packbf(acc1[2*t][2] + b0.x,   acc1[2*t][3] + b0.y);
                a2[t*4+2] = packbf(acc1[2*t+1][0] + b1.x, acc1[2*t+1][1] + b1.y);
                a2[t*4+3] = packbf(acc1[2*t+1][2] + b1.x, acc1[2*t+1][3] + b1.y);
            }
            const int r0 = ti * 16 + g, r1 = r0 + 8;
#pragma unroll 1
            for (int h2 = 0; h2 < 2; ++h2) {
                const int wb = h2 ? VU : KU;
                const int nb = h2 * 128;
                float acc2[16][4];
#pragma unroll
                for (int nt = 0; nt < 16; ++nt) {
                    const int c = nb + nt * 8 + 2 * tg;
                    const float2 bp = *reinterpret_cast<const float2*>(b_op + c);
                    float2 tA = make_float2(0.f, 0.f), tB = make_float2(0.f, 0.f);
                    if (r0 < NT) tA = *reinterpret_cast<const float2*>(
                        turb_s + (size_t)r0 * CM + c);
                    if (r1 < NT) tB = *reinterpret_cast<const float2*>(
                        turb_s + (size_t)r1 * CM + c);
                    acc2[nt][0] = bp.x + tA.x; acc2[nt][1] = bp.y + tA.y;
                    acc2[nt][2] = bp.x + tB.x; acc2[nt][3] = bp.y + tB.y;
                }
#pragma unroll
                for (int ks = 0; ks < 4; ++ks)
#pragma unroll
                    for (int nt = 0; nt < 16; ++nt) {
                        const int br = wb + (nt * 8 + g) * 36 + ks * 8 + tg;
                        mma16816(acc2[nt], &a2[ks * 4], smu[br], smu[br + 4]);
                    }
#pragma unroll
                for (int nt = 0; nt < 16; ++nt) {
                    const int c = nb + nt * 8 + 2 * tg;
                    if (r0 < NT)
                        *reinterpret_cast<float2*>(out_s + (size_t)r0 * CM + c) =
                            make_float2(acc2[nt][0], acc2[nt][1]);
                    if (r1 < NT)
                        *reinterpret_cast<float2*>(out_s + (size_t)r1 * CM + c) =
                            make_float2(acc2[nt][2], acc2[nt][3]);
                }
            }
        }
    }
}

extern "C" void kernel_launch(void* const* d_in, const int* in_sizes, int n_in,
                              void* d_out, int out_size)
{
    const float* turb  = (const float*)d_in[0];
    const float* weath = (const float*)d_in[1];
    const float* w_t   = (const float*)d_in[2];
    const float* b_t   = (const float*)d_in[3];
    const float* w_w   = (const float*)d_in[4];
    const float* b_w   = (const float*)d_in[5];
    const float* g_t   = (const float*)d_in[6];
    const float* be_t  = (const float*)d_in[7];
    const float* g_w   = (const float*)d_in[8];
    const float* be_w  = (const float*)d_in[9];
    const float* w_qkv = (const float*)d_in[10];
    const float* b_qkv = (const float*)d_in[11];
    const float* w_ao  = (const float*)d_in[12];
    const float* b_ao  = (const float*)d_in[13];
    const float* w_op  = (const float*)d_in[14];
    const float* b_op  = (const float*)d_in[15];
    float* out = (float*)d_out;

    const int S = in_sizes[0] / (NT * CM);   // 768
    const size_t smem = (size_t)SMEM_U * sizeof(unsigned);
    cudaFuncSetAttribute(wda_kernel, cudaFuncAttributeMaxDynamicSharedMemorySize,
                         (int)smem);
    wda_kernel<<<S, NTHR, smem>>>(turb, weath, w_t, b_t, w_w, b_w,
                                  g_t, be_t, g_w, be_w, w_qkv, b_qkv,
                                  w_ao, b_ao, w_op, b_op, out);
}